// round 6
// baseline (speedup 1.0000x reference)
#include <cuda_runtime.h>
#include <cuda_bf16.h>
#include <math.h>
#include <stdint.h>

// ---------------------------------------------------------------------------
// Problem constants
// ---------------------------------------------------------------------------
#define BB 256      // batch
#define TT 128      // timesteps
#define HH 2048     // hidden
#define CC 10       // classes

// ---------------------------------------------------------------------------
// Tiling: CTA 64x64 output, 512 threads = 4 K-groups of 4 warps.
// Group g handles K in [g*512, (g+1)*512), BK=32, 16 k-iters,
// 3-stage cp.async pipeline per group, XOR-swizzled 64B smem rows.
// Warp layout per group: 2m x 2n, warp tile 32x32.
// ---------------------------------------------------------------------------
#define BM 64
#define BN 64
#define BK 32
#define NGRP 4
#define KSPLIT (HH / NGRP)   // 512
#define NKT (KSPLIT / BK)    // 16
#define NTH 512
#define NSTG 3

#define ROWB 64                          // 32 bf16, no padding (swizzled)
#define BUFB (64 * ROWB)                 // one 64-row buffer: 4096 B
#define GSTAGE (4 * BUFB)                // Ahi,Alo,Whi,Wlo: 16384 B
#define GPIPE (NSTG * GSTAGE)            // 49152 B
#define SMEM_TOTAL (NGRP * GPIPE)        // 196608 B

// ---------------------------------------------------------------------------
// Device-global scratch (allocation-free)
// ---------------------------------------------------------------------------
__device__ __nv_bfloat16 g_whi[HH * HH];
__device__ __nv_bfloat16 g_wlo[HH * HH];
__device__ __nv_bfloat16 g_hhi[2][BB * HH];
__device__ __nv_bfloat16 g_hlo[2][BB * HH];

// ---------------------------------------------------------------------------
// PTX helpers (base-arch features only)
// ---------------------------------------------------------------------------
__device__ __forceinline__ uint32_t smem_u32(const void* p) {
    uint32_t a;
    asm("{ .reg .u64 t; cvta.to.shared.u64 t, %1; cvt.u32.u64 %0, t; }"
        : "=r"(a) : "l"(p));
    return a;
}
__device__ __forceinline__ void cp16(uint32_t dst, const void* src) {
    asm volatile("cp.async.cg.shared.global [%0], [%1], 16;"
                 :: "r"(dst), "l"(src) : "memory");
}
__device__ __forceinline__ void cp_commit() {
    asm volatile("cp.async.commit_group;" ::: "memory");
}
__device__ __forceinline__ void cp_wait1() {
    asm volatile("cp.async.wait_group 1;" ::: "memory");
}
__device__ __forceinline__ void barg(int id) {   // per-group barrier, 128 thr
    asm volatile("bar.sync %0, 128;" :: "r"(id) : "memory");
}
__device__ __forceinline__ void barall() {       // full CTA
    asm volatile("bar.sync 0, 512;" ::: "memory");
}
__device__ __forceinline__ void ldsm4(uint32_t* r, uint32_t addr) {
    asm volatile("ldmatrix.sync.aligned.m8n8.x4.shared.b16 {%0,%1,%2,%3}, [%4];"
                 : "=r"(r[0]), "=r"(r[1]), "=r"(r[2]), "=r"(r[3]) : "r"(addr));
}
__device__ __forceinline__ void mma_bf16(float* c, const uint32_t* a, const uint32_t* b) {
    asm volatile(
        "mma.sync.aligned.m16n8k16.row.col.f32.bf16.bf16.f32 "
        "{%0,%1,%2,%3}, {%4,%5,%6,%7}, {%8,%9}, {%0,%1,%2,%3};"
        : "+f"(c[0]), "+f"(c[1]), "+f"(c[2]), "+f"(c[3])
        : "r"(a[0]), "r"(a[1]), "r"(a[2]), "r"(a[3]), "r"(b[0]), "r"(b[1]));
}

// ---------------------------------------------------------------------------
// Prep kernels
// ---------------------------------------------------------------------------
__global__ void k_convert_w(const float* __restrict__ W) {
    int i = blockIdx.x * blockDim.x + threadIdx.x;
    if (i < HH * HH) {
        float w = W[i];
        __nv_bfloat16 hi = __float2bfloat16(w);
        g_whi[i] = hi;
        g_wlo[i] = __float2bfloat16(w - __bfloat162float(hi));
    }
}
__global__ void k_init_h() {
    int i = blockIdx.x * blockDim.x + threadIdx.x;
    if (i < BB * HH) {
        g_hhi[0][i] = __float2bfloat16(0.0f);
        g_hlo[0][i] = __float2bfloat16(0.0f);
    }
}

// ---------------------------------------------------------------------------
// One RNN step: D = (hhi+hlo) @ (Whi+Wlo)^T  (3-term bf16 split on HMMA)
// ---------------------------------------------------------------------------
__global__ __launch_bounds__(NTH, 1)
void rnn_step_hmma(const __nv_bfloat16* __restrict__ hhi_in,
                   const __nv_bfloat16* __restrict__ hlo_in,
                   const float* __restrict__ x,
                   const float* __restrict__ U,
                   const float* __restrict__ bh,
                   __nv_bfloat16* __restrict__ hhi_out,
                   __nv_bfloat16* __restrict__ hlo_out,
                   float* __restrict__ fout,
                   int t, int is_last) {
    extern __shared__ __align__(128) char smem[];
    const uint32_t sbase = smem_u32(smem);

    const int tid  = threadIdx.x;
    const int wid  = tid >> 5;
    const int lane = tid & 31;
    const int grp  = tid >> 7;           // 0..3
    const int gwid = wid & 3;
    const int gtid = tid & 127;
    const int n0 = blockIdx.x * BN;
    const int m0 = blockIdx.y * BM;

    const int wm = gwid & 1;
    const int wn = gwid >> 1;
    const int qid = lane >> 2;
    const int rid = lane & 3;

    const uint32_t gbase = sbase + (uint32_t)grp * GPIPE;
    const int kbase = grp * KSPLIT;

    // ---- cp.async mapping: per buffer rows r0, r0+32; chunk (gtid&3) swizzled
    const int r0  = gtid >> 2;           // 0..31
    const int cch = gtid & 3;            // chunk 0..3 (8 bf16 = 16 B)
    const int cbf = cch * 8;

    const __nv_bfloat16* gsrc[4];
    gsrc[0] = hhi_in + (size_t)(m0 + r0) * HH + kbase + cbf;
    gsrc[1] = hlo_in + (size_t)(m0 + r0) * HH + kbase + cbf;
    gsrc[2] = g_whi  + (size_t)(n0 + r0) * HH + kbase + cbf;
    gsrc[3] = g_wlo  + (size_t)(n0 + r0) * HH + kbase + cbf;

    const int swz = ((cch ^ ((r0 >> 1) & 3)) << 4);
    uint32_t sdst[4];
    #pragma unroll
    for (int bf = 0; bf < 4; bf++)
        sdst[bf] = gbase + (uint32_t)(bf * BUFB + r0 * ROWB) + swz;
    // row r0+32 swizzle identical ((r0+32)>>1 & 3 == (r0>>1)&3): dst + 32*ROWB

    // ---- ldmatrix addressing (swizzled) ----
    const int a_row = (lane & 7) + 8 * ((lane >> 3) & 1);
    const int a_c   = lane >> 4;                 // chunk offset within kh
    const int b_row = ((lane >> 4) << 3) + (lane & 7);
    const int b_c   = (lane >> 3) & 1;

    int rowsA[2], rowsB[2];
    rowsA[0] = wm * 32 + a_row;       rowsA[1] = rowsA[0] + 16;
    rowsB[0] = wn * 32 + b_row;       rowsB[1] = rowsB[0] + 16;

    uint32_t baseA[2], baseB[2];
    int offA[2][2], offB[2][2];       // [tile][kh]
    #pragma unroll
    for (int i = 0; i < 2; i++) {
        baseA[i] = gbase + (uint32_t)(0 * BUFB + rowsA[i] * ROWB);
        baseB[i] = gbase + (uint32_t)(2 * BUFB + rowsB[i] * ROWB);
        #pragma unroll
        for (int kh = 0; kh < 2; kh++) {
            offA[i][kh] = (((kh * 2 + a_c) ^ ((rowsA[i] >> 1) & 3)) << 4);
            offB[i][kh] = (((kh * 2 + b_c) ^ ((rowsB[i] >> 1) & 3)) << 4);
        }
    }

    float acc[2][4][4];
    #pragma unroll
    for (int i = 0; i < 2; i++)
        #pragma unroll
        for (int j = 0; j < 4; j++)
            #pragma unroll
            for (int e = 0; e < 4; e++) acc[i][j][e] = 0.0f;

    // ---- prologue: stages 0 and 1 ----
    #pragma unroll
    for (int s = 0; s < 2; s++) {
        const uint32_t so = (uint32_t)s * GSTAGE;
        const int kk = s * BK;
        #pragma unroll
        for (int bf = 0; bf < 4; bf++) {
            cp16(sdst[bf] + so,             gsrc[bf] + kk);
            cp16(sdst[bf] + so + 32 * ROWB, gsrc[bf] + kk + (size_t)32 * HH);
        }
        cp_commit();
    }

    const int mybar = grp + 1;
    uint32_t so = 0;                  // current stage offset
    uint32_t so_nxt = 2 * GSTAGE;     // slot for kt+2

    for (int kt = 0; kt < NKT; kt++) {
        cp_wait1();
        barg(mybar);

        // ---- ldsm: all fragments for this stage (both kh) ----
        uint32_t ahi[2][2][4], alo[2][2][4];   // [kh][mt]
        uint32_t bhi[2][8], blo[2][8];         // [kh]
        #pragma unroll
        for (int kh = 0; kh < 2; kh++) {
            #pragma unroll
            for (int mt = 0; mt < 2; mt++) {
                ldsm4(ahi[kh][mt], baseA[mt] + offA[mt][kh] + so);
                ldsm4(alo[kh][mt], baseA[mt] + offA[mt][kh] + so + BUFB);
            }
            ldsm4(bhi[kh],     baseB[0] + offB[0][kh] + so);
            ldsm4(bhi[kh] + 4, baseB[1] + offB[1][kh] + so);
            ldsm4(blo[kh],     baseB[0] + offB[0][kh] + so + BUFB);
            ldsm4(blo[kh] + 4, baseB[1] + offB[1][kh] + so + BUFB);
        }

        // ---- prefetch stage kt+2 (flies during MMA burst) ----
        if (kt + 2 < NKT) {
            const int kk = (kt + 2) * BK;
            #pragma unroll
            for (int bf = 0; bf < 4; bf++) {
                cp16(sdst[bf] + so_nxt,             gsrc[bf] + kk);
                cp16(sdst[bf] + so_nxt + 32 * ROWB, gsrc[bf] + kk + (size_t)32 * HH);
            }
        }
        cp_commit();

        // ---- 48 MMAs ----
        #pragma unroll
        for (int kh = 0; kh < 2; kh++)
            #pragma unroll
            for (int mt = 0; mt < 2; mt++)
                #pragma unroll
                for (int nt = 0; nt < 4; nt++) {
                    mma_bf16(acc[mt][nt], ahi[kh][mt], bhi[kh] + 2 * nt);
                    mma_bf16(acc[mt][nt], ahi[kh][mt], blo[kh] + 2 * nt);
                    mma_bf16(acc[mt][nt], alo[kh][mt], bhi[kh] + 2 * nt);
                }

        so     = (so     == 2 * GSTAGE) ? 0 : so + GSTAGE;
        so_nxt = (so_nxt == 2 * GSTAGE) ? 0 : so_nxt + GSTAGE;
    }
    barg(mybar);   // group's reads done before aliasing its region as exchange

    // ---- every group publishes acc into its own (dead) stage-0 region ----
    {
        float2* exg = (float2*)(smem + grp * GPIPE);
        #pragma unroll
        for (int mt = 0; mt < 2; mt++)
            #pragma unroll
            for (int nt = 0; nt < 4; nt++) {
                const int p = (mt * 4 + nt) * 2;
                exg[p * 128 + gtid]       = make_float2(acc[mt][nt][0], acc[mt][nt][1]);
                exg[(p + 1) * 128 + gtid] = make_float2(acc[mt][nt][2], acc[mt][nt][3]);
            }
    }
    barall();

    // ---- distributed combine + epilogue: thread handles 4 pairs (8 outputs) --
    {
        const int myMt   = grp >> 1;          // pglob>>3 for pglob in [4g,4g+4)
        const int ntBase = (grp & 1) * 2;
        const int row0 = m0 + wm * 32 + myMt * 16 + qid;
        const float x0 = x[(size_t)row0 * TT + t];
        const float x1 = x[(size_t)(row0 + 8) * TT + t];

        #pragma unroll
        for (int p = 0; p < 4; p++) {
            const int pglob = grp * 4 + p;
            const int nt = ntBase + (p >> 1);
            const int eh = p & 1;
            const int j  = n0 + wn * 32 + nt * 8 + rid * 2;
            const int row = row0 + eh * 8;
            const float xb = eh ? x1 : x0;

            float sx = 0.0f, sy = 0.0f;
            #pragma unroll
            for (int g = 0; g < 4; g++) {
                float2 v = ((float2*)(smem + g * GPIPE))[pglob * 128 + gtid];
                sx += v.x; sy += v.y;
            }
            const float v0 = tanhf(sx + xb * U[j]     + bh[j]);
            const float v1 = tanhf(sy + xb * U[j + 1] + bh[j + 1]);

            __nv_bfloat16 hh0 = __float2bfloat16(v0);
            __nv_bfloat16 hh1 = __float2bfloat16(v1);
            __nv_bfloat16 ll0 = __float2bfloat16(v0 - __bfloat162float(hh0));
            __nv_bfloat16 ll1 = __float2bfloat16(v1 - __bfloat162float(hh1));
            unsigned short s0 = *(unsigned short*)&hh0;
            unsigned short s1 = *(unsigned short*)&hh1;
            unsigned short w0 = *(unsigned short*)&ll0;
            unsigned short w1 = *(unsigned short*)&ll1;
            *(uint32_t*)(hhi_out + (size_t)row * HH + j) = (uint32_t)s0 | ((uint32_t)s1 << 16);
            *(uint32_t*)(hlo_out + (size_t)row * HH + j) = (uint32_t)w0 | ((uint32_t)w1 << 16);
            if (is_last) {
                fout[(size_t)row * HH + j]     = v0;
                fout[(size_t)row * HH + j + 1] = v1;
            }
        }
    }
}

// ---------------------------------------------------------------------------
// Head: out[b,c] = sum_k h[b,k]*V[c,k] + bp[c]
// ---------------------------------------------------------------------------
__global__ __launch_bounds__(256)
void rnn_head_kernel(const float* __restrict__ h,
                     const float* __restrict__ V,
                     const float* __restrict__ bp,
                     float* __restrict__ out) {
    const int b = blockIdx.x;
    const int tid = threadIdx.x;
    __shared__ float red[256];

    float partial[CC];
    #pragma unroll
    for (int c = 0; c < CC; c++) partial[c] = 0.0f;

    const float* hrow = h + (size_t)b * HH;
    for (int k = tid; k < HH; k += 256) {
        float hv = hrow[k];
        #pragma unroll
        for (int c = 0; c < CC; c++)
            partial[c] = fmaf(hv, V[(size_t)c * HH + k], partial[c]);
    }

    for (int c = 0; c < CC; c++) {
        red[tid] = partial[c];
        __syncthreads();
        for (int s = 128; s > 0; s >>= 1) {
            if (tid < s) red[tid] += red[tid + s];
            __syncthreads();
        }
        if (tid == 0) out[(size_t)b * CC + c] = red[0] + bp[c];
        __syncthreads();
    }
}

// ---------------------------------------------------------------------------
// Host launch
// ---------------------------------------------------------------------------
extern "C" void kernel_launch(void* const* d_in, const int* in_sizes, int n_in,
                              void* d_out, int out_size) {
    const float* x  = (const float*)d_in[0];   // [B, T]
    const float* U  = (const float*)d_in[1];   // [H, 1]
    const float* W  = (const float*)d_in[2];   // [H, H]
    const float* V  = (const float*)d_in[3];   // [C, H]
    const float* bh = (const float*)d_in[4];   // [H]
    const float* bp = (const float*)d_in[5];   // [C]
    float* out = (float*)d_out;                // [B*H + B*C]

    cudaFuncSetAttribute(rnn_step_hmma,
                         cudaFuncAttributeMaxDynamicSharedMemorySize, SMEM_TOTAL);

    void *p_hhi, *p_hlo;
    cudaGetSymbolAddress(&p_hhi, g_hhi);
    cudaGetSymbolAddress(&p_hlo, g_hlo);
    __nv_bfloat16* hhi = (__nv_bfloat16*)p_hhi;
    __nv_bfloat16* hlo = (__nv_bfloat16*)p_hlo;

    // prep: split W into bf16 hi/lo, zero h0
    k_convert_w<<<(HH * HH + 255) / 256, 256>>>(W);
    k_init_h<<<(BB * HH + 255) / 256, 256>>>();

    // 128 sequential steps, ping-pong bf16 hidden state
    dim3 grid(HH / BN, BB / BM);  // (32, 4) = 128 CTAs
    for (int t = 0; t < TT; t++) {
        const int inb  = t & 1;
        const int outb = inb ^ 1;
        rnn_step_hmma<<<grid, NTH, SMEM_TOTAL>>>(
            hhi + (size_t)inb * BB * HH,
            hlo + (size_t)inb * BB * HH,
            x, U, bh,
            hhi + (size_t)outb * BB * HH,
            hlo + (size_t)outb * BB * HH,
            out, t, (t == TT - 1) ? 1 : 0);
    }

    // head on fp32 h_last (written into d_out by last step)
    rnn_head_kernel<<<BB, 256>>>(out, V, bp, out + (size_t)BB * HH);
}

// round 7
// speedup vs baseline: 1.0765x; 1.0765x over previous
#include <cuda_runtime.h>
#include <cuda_bf16.h>
#include <math.h>
#include <stdint.h>

// ---------------------------------------------------------------------------
// Problem constants
// ---------------------------------------------------------------------------
#define BB 256      // batch
#define TT 128      // timesteps
#define HH 2048     // hidden
#define CC 10       // classes

// ---------------------------------------------------------------------------
// Tiling: CTA 64x64 output, 512 threads = 4 K-groups of 4 warps.
// Group g handles K in [g*512, (g+1)*512), BK=32, 16 k-iters,
// 3-stage cp.async pipeline per group, XOR-swizzled 64B smem rows,
// ONE group barrier per k-iter. Warp layout per group: 2m x 2n, tile 32x32.
// ---------------------------------------------------------------------------
#define BM 64
#define BN 64
#define BK 32
#define NGRP 4
#define KSPLIT (HH / NGRP)   // 512
#define NKT (KSPLIT / BK)    // 16
#define NTH 512
#define NSTG 3

#define ROWB 64                          // 32 bf16, no padding (swizzled)
#define BUFB (64 * ROWB)                 // 4096 B
#define GSTAGE (4 * BUFB)                // Ahi,Alo,Whi,Wlo: 16384 B
#define GPIPE (NSTG * GSTAGE)            // 49152 B
#define SMEM_TOTAL (NGRP * GPIPE)        // 196608 B

// ---------------------------------------------------------------------------
// Device-global scratch (allocation-free)
// ---------------------------------------------------------------------------
__device__ __nv_bfloat16 g_whi[HH * HH];
__device__ __nv_bfloat16 g_wlo[HH * HH];
__device__ __nv_bfloat16 g_hhi[2][BB * HH];
__device__ __nv_bfloat16 g_hlo[2][BB * HH];

// ---------------------------------------------------------------------------
// PTX helpers (base-arch features only)
// ---------------------------------------------------------------------------
__device__ __forceinline__ uint32_t smem_u32(const void* p) {
    uint32_t a;
    asm("{ .reg .u64 t; cvta.to.shared.u64 t, %1; cvt.u32.u64 %0, t; }"
        : "=r"(a) : "l"(p));
    return a;
}
__device__ __forceinline__ void cp16(uint32_t dst, const void* src) {
    asm volatile("cp.async.cg.shared.global [%0], [%1], 16;"
                 :: "r"(dst), "l"(src) : "memory");
}
__device__ __forceinline__ void cp_commit() {
    asm volatile("cp.async.commit_group;" ::: "memory");
}
__device__ __forceinline__ void cp_wait1() {
    asm volatile("cp.async.wait_group 1;" ::: "memory");
}
__device__ __forceinline__ void barg(int id) {   // per-group barrier, 128 thr
    asm volatile("bar.sync %0, 128;" :: "r"(id) : "memory");
}
__device__ __forceinline__ void barall() {       // full CTA
    asm volatile("bar.sync 0, 512;" ::: "memory");
}
__device__ __forceinline__ void ldsm4(uint32_t* r, uint32_t addr) {
    asm volatile("ldmatrix.sync.aligned.m8n8.x4.shared.b16 {%0,%1,%2,%3}, [%4];"
                 : "=r"(r[0]), "=r"(r[1]), "=r"(r[2]), "=r"(r[3]) : "r"(addr));
}
__device__ __forceinline__ void mma_bf16(float* c, const uint32_t* a, const uint32_t* b) {
    asm volatile(
        "mma.sync.aligned.m16n8k16.row.col.f32.bf16.bf16.f32 "
        "{%0,%1,%2,%3}, {%4,%5,%6,%7}, {%8,%9}, {%0,%1,%2,%3};"
        : "+f"(c[0]), "+f"(c[1]), "+f"(c[2]), "+f"(c[3])
        : "r"(a[0]), "r"(a[1]), "r"(a[2]), "r"(a[3]), "r"(b[0]), "r"(b[1]));
}

// ---------------------------------------------------------------------------
// Prep kernels
// ---------------------------------------------------------------------------
__global__ void k_convert_w(const float* __restrict__ W) {
    int i = blockIdx.x * blockDim.x + threadIdx.x;
    if (i < HH * HH) {
        float w = W[i];
        __nv_bfloat16 hi = __float2bfloat16(w);
        g_whi[i] = hi;
        g_wlo[i] = __float2bfloat16(w - __bfloat162float(hi));
    }
}
__global__ void k_init_h() {
    int i = blockIdx.x * blockDim.x + threadIdx.x;
    if (i < BB * HH) {
        g_hhi[0][i] = __float2bfloat16(0.0f);
        g_hlo[0][i] = __float2bfloat16(0.0f);
    }
}

// ---------------------------------------------------------------------------
// One RNN step: D = (hhi+hlo) @ (Whi+Wlo)^T  (3-term bf16 split on HMMA)
// ---------------------------------------------------------------------------
__global__ __launch_bounds__(NTH, 1)
void rnn_step_hmma(const __nv_bfloat16* __restrict__ hhi_in,
                   const __nv_bfloat16* __restrict__ hlo_in,
                   const float* __restrict__ x,
                   const float* __restrict__ U,
                   const float* __restrict__ bh,
                   __nv_bfloat16* __restrict__ hhi_out,
                   __nv_bfloat16* __restrict__ hlo_out,
                   float* __restrict__ fout,
                   int t, int is_last) {
    extern __shared__ __align__(128) char smem[];
    const uint32_t sbase = smem_u32(smem);

    const int tid  = threadIdx.x;
    const int wid  = tid >> 5;
    const int lane = tid & 31;
    const int grp  = tid >> 7;           // 0..3
    const int gwid = wid & 3;
    const int gtid = tid & 127;
    const int n0 = blockIdx.x * BN;
    const int m0 = blockIdx.y * BM;

    const int wm = gwid & 1;
    const int wn = gwid >> 1;
    const int qid = lane >> 2;
    const int rid = lane & 3;

    const uint32_t gbase = sbase + (uint32_t)grp * GPIPE;
    const int kbase = grp * KSPLIT;

    // ---- cp.async mapping: per buffer rows r0, r0+32; chunk (gtid&3) swizzled
    const int r0  = gtid >> 2;           // 0..31
    const int cch = gtid & 3;            // 16B chunk id
    const int cbf = cch * 8;

    const __nv_bfloat16* gsrc[4];
    gsrc[0] = hhi_in + (size_t)(m0 + r0) * HH + kbase + cbf;
    gsrc[1] = hlo_in + (size_t)(m0 + r0) * HH + kbase + cbf;
    gsrc[2] = g_whi  + (size_t)(n0 + r0) * HH + kbase + cbf;
    gsrc[3] = g_wlo  + (size_t)(n0 + r0) * HH + kbase + cbf;

    const int swz = ((cch ^ ((r0 >> 1) & 3)) << 4);
    uint32_t sdst[4];
    #pragma unroll
    for (int bf = 0; bf < 4; bf++)
        sdst[bf] = gbase + (uint32_t)(bf * BUFB + r0 * ROWB) + swz;

    // ---- ldmatrix addressing (swizzled) ----
    const int a_row = (lane & 7) + 8 * ((lane >> 3) & 1);
    const int a_c   = lane >> 4;
    const int b_row = ((lane >> 4) << 3) + (lane & 7);
    const int b_c   = (lane >> 3) & 1;

    int rowsA[2], rowsB[2];
    rowsA[0] = wm * 32 + a_row;       rowsA[1] = rowsA[0] + 16;
    rowsB[0] = wn * 32 + b_row;       rowsB[1] = rowsB[0] + 16;

    uint32_t baseA[2], baseB[2];
    int offA[2][2], offB[2][2];       // [tile][kh]
    #pragma unroll
    for (int i = 0; i < 2; i++) {
        baseA[i] = gbase + (uint32_t)(0 * BUFB + rowsA[i] * ROWB);
        baseB[i] = gbase + (uint32_t)(2 * BUFB + rowsB[i] * ROWB);
        #pragma unroll
        for (int kh = 0; kh < 2; kh++) {
            offA[i][kh] = (((kh * 2 + a_c) ^ ((rowsA[i] >> 1) & 3)) << 4);
            offB[i][kh] = (((kh * 2 + b_c) ^ ((rowsB[i] >> 1) & 3)) << 4);
        }
    }

    float acc[2][4][4];
    #pragma unroll
    for (int i = 0; i < 2; i++)
        #pragma unroll
        for (int j = 0; j < 4; j++)
            #pragma unroll
            for (int e = 0; e < 4; e++) acc[i][j][e] = 0.0f;

    // ---- prologue: stages 0 and 1 ----
    #pragma unroll
    for (int s = 0; s < 2; s++) {
        const uint32_t so0 = (uint32_t)s * GSTAGE;
        const int kk = s * BK;
        #pragma unroll
        for (int bf = 0; bf < 4; bf++) {
            cp16(sdst[bf] + so0,             gsrc[bf] + kk);
            cp16(sdst[bf] + so0 + 32 * ROWB, gsrc[bf] + kk + (size_t)32 * HH);
        }
        cp_commit();
    }

    const int mybar = grp + 1;
    uint32_t so = 0;
    uint32_t so_nxt = 2 * GSTAGE;

    for (int kt = 0; kt < NKT; kt++) {
        cp_wait1();
        barg(mybar);   // stage kt visible to group; also seals reads of stage so_nxt

        // ---- prefetch stage kt+2 (flies during ldsm+MMA) ----
        if (kt + 2 < NKT) {
            const int kk = (kt + 2) * BK;
            #pragma unroll
            for (int bf = 0; bf < 4; bf++) {
                cp16(sdst[bf] + so_nxt,             gsrc[bf] + kk);
                cp16(sdst[bf] + so_nxt + 32 * ROWB, gsrc[bf] + kk + (size_t)32 * HH);
            }
        }
        cp_commit();

        // ---- per-kh: ldsm then 24 MMAs (keeps register lifetimes short) ----
        #pragma unroll
        for (int kh = 0; kh < 2; kh++) {
            uint32_t ahi[2][4], alo[2][4];
            #pragma unroll
            for (int mt = 0; mt < 2; mt++) {
                ldsm4(ahi[mt], baseA[mt] + offA[mt][kh] + so);
                ldsm4(alo[mt], baseA[mt] + offA[mt][kh] + so + BUFB);
            }
            uint32_t bhi[8], blo[8];
            ldsm4(bhi,     baseB[0] + offB[0][kh] + so);
            ldsm4(bhi + 4, baseB[1] + offB[1][kh] + so);
            ldsm4(blo,     baseB[0] + offB[0][kh] + so + BUFB);
            ldsm4(blo + 4, baseB[1] + offB[1][kh] + so + BUFB);

            #pragma unroll
            for (int mt = 0; mt < 2; mt++)
                #pragma unroll
                for (int nt = 0; nt < 4; nt++) {
                    mma_bf16(acc[mt][nt], ahi[mt], bhi + 2 * nt);
                    mma_bf16(acc[mt][nt], ahi[mt], blo + 2 * nt);
                    mma_bf16(acc[mt][nt], alo[mt], bhi + 2 * nt);
                }
        }

        so     = (so     == 2 * GSTAGE) ? 0 : so + GSTAGE;
        so_nxt = (so_nxt == 2 * GSTAGE) ? 0 : so_nxt + GSTAGE;
    }
    barg(mybar);   // group reads done before aliasing stage-0 region

    // ---- every group publishes acc into its own (dead) stage-0 region ----
    {
        float2* exg = (float2*)(smem + grp * GPIPE);
        #pragma unroll
        for (int mt = 0; mt < 2; mt++)
            #pragma unroll
            for (int nt = 0; nt < 4; nt++) {
                const int p = (mt * 4 + nt) * 2;
                exg[p * 128 + gtid]       = make_float2(acc[mt][nt][0], acc[mt][nt][1]);
                exg[(p + 1) * 128 + gtid] = make_float2(acc[mt][nt][2], acc[mt][nt][3]);
            }
    }
    barall();

    // ---- distributed combine + epilogue: each thread 4 pairs (8 outputs) ----
    {
        const int myMt   = grp >> 1;
        const int ntBase = (grp & 1) * 2;
        const int row0 = m0 + wm * 32 + myMt * 16 + qid;
        const float x0 = x[(size_t)row0 * TT + t];
        const float x1 = x[(size_t)(row0 + 8) * TT + t];

        #pragma unroll
        for (int p = 0; p < 4; p++) {
            const int pglob = grp * 4 + p;
            const int nt = ntBase + (p >> 1);
            const int eh = p & 1;
            const int j  = n0 + wn * 32 + nt * 8 + rid * 2;
            const int row = row0 + eh * 8;
            const float xb = eh ? x1 : x0;

            float sx = 0.0f, sy = 0.0f;
            #pragma unroll
            for (int g = 0; g < 4; g++) {
                float2 v = ((float2*)(smem + g * GPIPE))[pglob * 128 + gtid];
                sx += v.x; sy += v.y;
            }
            const float v0 = tanhf(sx + xb * U[j]     + bh[j]);
            const float v1 = tanhf(sy + xb * U[j + 1] + bh[j + 1]);

            __nv_bfloat16 hh0 = __float2bfloat16(v0);
            __nv_bfloat16 hh1 = __float2bfloat16(v1);
            __nv_bfloat16 ll0 = __float2bfloat16(v0 - __bfloat162float(hh0));
            __nv_bfloat16 ll1 = __float2bfloat16(v1 - __bfloat162float(hh1));
            unsigned short s0 = *(unsigned short*)&hh0;
            unsigned short s1 = *(unsigned short*)&hh1;
            unsigned short w0 = *(unsigned short*)&ll0;
            unsigned short w1 = *(unsigned short*)&ll1;
            *(uint32_t*)(hhi_out + (size_t)row * HH + j) = (uint32_t)s0 | ((uint32_t)s1 << 16);
            *(uint32_t*)(hlo_out + (size_t)row * HH + j) = (uint32_t)w0 | ((uint32_t)w1 << 16);
            if (is_last) {
                fout[(size_t)row * HH + j]     = v0;
                fout[(size_t)row * HH + j + 1] = v1;
            }
        }
    }
}

// ---------------------------------------------------------------------------
// Head: out[b,c] = sum_k h[b,k]*V[c,k] + bp[c]
// ---------------------------------------------------------------------------
__global__ __launch_bounds__(256)
void rnn_head_kernel(const float* __restrict__ h,
                     const float* __restrict__ V,
                     const float* __restrict__ bp,
                     float* __restrict__ out) {
    const int b = blockIdx.x;
    const int tid = threadIdx.x;
    __shared__ float red[256];

    float partial[CC];
    #pragma unroll
    for (int c = 0; c < CC; c++) partial[c] = 0.0f;

    const float* hrow = h + (size_t)b * HH;
    for (int k = tid; k < HH; k += 256) {
        float hv = hrow[k];
        #pragma unroll
        for (int c = 0; c < CC; c++)
            partial[c] = fmaf(hv, V[(size_t)c * HH + k], partial[c]);
    }

    for (int c = 0; c < CC; c++) {
        red[tid] = partial[c];
        __syncthreads();
        for (int s = 128; s > 0; s >>= 1) {
            if (tid < s) red[tid] += red[tid + s];
            __syncthreads();
        }
        if (tid == 0) out[(size_t)b * CC + c] = red[0] + bp[c];
        __syncthreads();
    }
}

// ---------------------------------------------------------------------------
// Host launch
// ---------------------------------------------------------------------------
extern "C" void kernel_launch(void* const* d_in, const int* in_sizes, int n_in,
                              void* d_out, int out_size) {
    const float* x  = (const float*)d_in[0];   // [B, T]
    const float* U  = (const float*)d_in[1];   // [H, 1]
    const float* W  = (const float*)d_in[2];   // [H, H]
    const float* V  = (const float*)d_in[3];   // [C, H]
    const float* bh = (const float*)d_in[4];   // [H]
    const float* bp = (const float*)d_in[5];   // [C]
    float* out = (float*)d_out;                // [B*H + B*C]

    cudaFuncSetAttribute(rnn_step_hmma,
                         cudaFuncAttributeMaxDynamicSharedMemorySize, SMEM_TOTAL);

    void *p_hhi, *p_hlo;
    cudaGetSymbolAddress(&p_hhi, g_hhi);
    cudaGetSymbolAddress(&p_hlo, g_hlo);
    __nv_bfloat16* hhi = (__nv_bfloat16*)p_hhi;
    __nv_bfloat16* hlo = (__nv_bfloat16*)p_hlo;

    // prep: split W into bf16 hi/lo, zero h0
    k_convert_w<<<(HH * HH + 255) / 256, 256>>>(W);
    k_init_h<<<(BB * HH + 255) / 256, 256>>>();

    // 128 sequential steps, ping-pong bf16 hidden state
    dim3 grid(HH / BN, BB / BM);  // (32, 4) = 128 CTAs
    for (int t = 0; t < TT; t++) {
        const int inb  = t & 1;
        const int outb = inb ^ 1;
        rnn_step_hmma<<<grid, NTH, SMEM_TOTAL>>>(
            hhi + (size_t)inb * BB * HH,
            hlo + (size_t)inb * BB * HH,
            x, U, bh,
            hhi + (size_t)outb * BB * HH,
            hlo + (size_t)outb * BB * HH,
            out, t, (t == TT - 1) ? 1 : 0);
    }

    // head on fp32 h_last (written into d_out by last step)
    rnn_head_kernel<<<BB, 256>>>(out, V, bp, out + (size_t)BB * HH);
}

// round 9
// speedup vs baseline: 1.2290x; 1.1416x over previous
#include <cuda_runtime.h>
#include <cuda_bf16.h>
#include <math.h>
#include <stdint.h>

// ---------------------------------------------------------------------------
// Problem constants
// ---------------------------------------------------------------------------
#define BB 256      // batch
#define TT 128      // timesteps
#define HH 2048     // hidden
#define CC 10       // classes

// ---------------------------------------------------------------------------
// R5 tiling (best measured): CTA 64x64, 512 threads = 4 K-groups x 4 warps.
// Group g: K in [g*512,(g+1)*512), BK=32, 16 k-iters, 2-stage cp.async pipe,
// padded 80B rows. Warp tile 32x32 (2m x 2n per group).
// Persistent: one launch, 128 steps, software global barrier between steps.
// ---------------------------------------------------------------------------
#define BM 64
#define BN 64
#define BK 32
#define NGRP 4
#define KSPLIT (HH / NGRP)   // 512
#define NKT (KSPLIT / BK)    // 16
#define NTH 512
#define NCTA 128

#define ROWB 80                          // 32 bf16 + 8 pad
#define BUFB (64 * ROWB)                 // 5120 B
#define GSTAGE (4 * BUFB)                // Ahi,Alo,Whi,Wlo: 20480 B
#define GPIPE (2 * GSTAGE)               // 40960 B
#define SMEM_TOTAL (NGRP * GPIPE)        // 163840 B (exchange aliases GPIPE)

// ---------------------------------------------------------------------------
// Device-global scratch (allocation-free)
// ---------------------------------------------------------------------------
__device__ __nv_bfloat16 g_whi[HH * HH];
__device__ __nv_bfloat16 g_wlo[HH * HH];
__device__ __nv_bfloat16 g_hhi[2][BB * HH];
__device__ __nv_bfloat16 g_hlo[2][BB * HH];
__device__ unsigned g_bar;

// ---------------------------------------------------------------------------
// PTX helpers (base-arch features only)
// ---------------------------------------------------------------------------
__device__ __forceinline__ uint32_t smem_u32(const void* p) {
    uint32_t a;
    asm("{ .reg .u64 t; cvta.to.shared.u64 t, %1; cvt.u32.u64 %0, t; }"
        : "=r"(a) : "l"(p));
    return a;
}
__device__ __forceinline__ void cp16(uint32_t dst, const void* src) {
    asm volatile("cp.async.cg.shared.global [%0], [%1], 16;"
                 :: "r"(dst), "l"(src) : "memory");
}
__device__ __forceinline__ void cp_commit() {
    asm volatile("cp.async.commit_group;" ::: "memory");
}
__device__ __forceinline__ void cp_wait1() {
    asm volatile("cp.async.wait_group 1;" ::: "memory");
}
__device__ __forceinline__ void cp_wait0() {
    asm volatile("cp.async.wait_group 0;" ::: "memory");
}
__device__ __forceinline__ void barg(int id) {   // per-group barrier, 128 thr
    asm volatile("bar.sync %0, 128;" :: "r"(id) : "memory");
}
__device__ __forceinline__ void barall() {       // full CTA
    asm volatile("bar.sync 0, 512;" ::: "memory");
}
__device__ __forceinline__ void ldsm4(uint32_t* r, uint32_t addr) {
    asm volatile("ldmatrix.sync.aligned.m8n8.x4.shared.b16 {%0,%1,%2,%3}, [%4];"
                 : "=r"(r[0]), "=r"(r[1]), "=r"(r[2]), "=r"(r[3]) : "r"(addr));
}
__device__ __forceinline__ void mma_bf16(float* c, const uint32_t* a, const uint32_t* b) {
    asm volatile(
        "mma.sync.aligned.m16n8k16.row.col.f32.bf16.bf16.f32 "
        "{%0,%1,%2,%3}, {%4,%5,%6,%7}, {%8,%9}, {%0,%1,%2,%3};"
        : "+f"(c[0]), "+f"(c[1]), "+f"(c[2]), "+f"(c[3])
        : "r"(a[0]), "r"(a[1]), "r"(a[2]), "r"(a[3]), "r"(b[0]), "r"(b[1]));
}

// ---------------------------------------------------------------------------
// Prep kernels
// ---------------------------------------------------------------------------
__global__ void k_convert_w(const float* __restrict__ W) {
    int i = blockIdx.x * blockDim.x + threadIdx.x;
    if (i < HH * HH) {
        float w = W[i];
        __nv_bfloat16 hi = __float2bfloat16(w);
        g_whi[i] = hi;
        g_wlo[i] = __float2bfloat16(w - __bfloat162float(hi));
    }
}
__global__ void k_init_h() {
    int i = blockIdx.x * blockDim.x + threadIdx.x;
    if (i < BB * HH) {
        g_hhi[0][i] = __float2bfloat16(0.0f);
        g_hlo[0][i] = __float2bfloat16(0.0f);
    }
    if (i == 0) g_bar = 0u;   // deterministic per launch (graph replay safe)
}

// ---------------------------------------------------------------------------
// Persistent RNN: all 128 steps in one launch.
// Step t: D = (hhi+hlo) @ (Whi+Wlo)^T  (3-term bf16 split on HMMA),
// h_{t+1} = tanh(D + x[:,t]*U + bh) re-split to bf16 hi/lo;
// software global barrier between steps (128 CTAs = one wave, all resident).
// ---------------------------------------------------------------------------
__global__ __launch_bounds__(NTH, 1)
void rnn_persist(const float* __restrict__ x,
                 const float* __restrict__ U,
                 const float* __restrict__ bh,
                 float* __restrict__ fout) {
    extern __shared__ __align__(128) char smem[];
    const uint32_t sbase = smem_u32(smem);

    const int tid  = threadIdx.x;
    const int wid  = tid >> 5;
    const int lane = tid & 31;
    const int grp  = tid >> 7;           // 0..3
    const int gwid = wid & 3;
    const int gtid = tid & 127;
    const int n0 = blockIdx.x * BN;
    const int m0 = blockIdx.y * BM;

    const int wm = gwid & 1;
    const int wn = gwid >> 1;
    const int qid = lane >> 2;
    const int rid = lane & 3;

    const uint32_t gbase = sbase + (uint32_t)grp * GPIPE;
    const int kbase = grp * KSPLIT;

    // ---- cp.async mapping (R5): per buffer rows r0, r0+32; 16B chunk ----
    const int r0  = gtid >> 2;           // 0..31
    const int cbf = (gtid & 3) * 8;      // bf16 col offset
    const int cby = (gtid & 3) * 16;     // byte col offset

    // W sources are step-invariant
    const __nv_bfloat16* gW0 = g_whi + (size_t)(n0 + r0) * HH + kbase + cbf;
    const __nv_bfloat16* gW1 = g_wlo + (size_t)(n0 + r0) * HH + kbase + cbf;

    uint32_t sdst[4];                    // stage-0 dsts for row r0
    #pragma unroll
    for (int bf = 0; bf < 4; bf++)
        sdst[bf] = gbase + (uint32_t)(bf * BUFB + r0 * ROWB + cby);

    // ---- ldmatrix lane addressing (R5, padded rows) ----
    const int a_row = (lane & 7) + 8 * ((lane >> 3) & 1);
    const int a_k   = 8 * (lane >> 4);
    const int b_row = ((lane >> 4) << 3) + (lane & 7);
    const int b_k   = ((lane >> 3) & 1) * 8;

    // epilogue constants
    const int myMt   = grp >> 1;
    const int ntBase = (grp & 1) * 2;
    const int erow0  = m0 + wm * 32 + myMt * 16 + qid;

    const int mybar = grp + 1;

    for (int t = 0; t < TT; t++) {
        const __nv_bfloat16* hhi_in = g_hhi[t & 1];
        const __nv_bfloat16* hlo_in = g_hlo[t & 1];
        __nv_bfloat16* hhi_out = g_hhi[(t + 1) & 1];
        __nv_bfloat16* hlo_out = g_hlo[(t + 1) & 1];

        const __nv_bfloat16* gA0 = hhi_in + (size_t)(m0 + r0) * HH + kbase + cbf;
        const __nv_bfloat16* gA1 = hlo_in + (size_t)(m0 + r0) * HH + kbase + cbf;

        float acc[2][4][4];
        #pragma unroll
        for (int i = 0; i < 2; i++)
            #pragma unroll
            for (int j = 0; j < 4; j++)
                #pragma unroll
                for (int e = 0; e < 4; e++) acc[i][j][e] = 0.0f;

        // ---- prologue: stage 0 ----
        cp16(sdst[0],             gA0);
        cp16(sdst[0] + 32 * ROWB, gA0 + (size_t)32 * HH);
        cp16(sdst[1],             gA1);
        cp16(sdst[1] + 32 * ROWB, gA1 + (size_t)32 * HH);
        cp16(sdst[2],             gW0);
        cp16(sdst[2] + 32 * ROWB, gW0 + (size_t)32 * HH);
        cp16(sdst[3],             gW1);
        cp16(sdst[3] + 32 * ROWB, gW1 + (size_t)32 * HH);
        cp_commit();

        // ---- mainloop (exact R5 rhythm) ----
        for (int kt = 0; kt < NKT; kt++) {
            const int cur = kt & 1;
            if (kt + 1 < NKT) {
                const uint32_t so = (uint32_t)((kt + 1) & 1) * GSTAGE;
                const int kk = (kt + 1) * BK;
                cp16(sdst[0] + so,             gA0 + kk);
                cp16(sdst[0] + so + 32 * ROWB, gA0 + kk + (size_t)32 * HH);
                cp16(sdst[1] + so,             gA1 + kk);
                cp16(sdst[1] + so + 32 * ROWB, gA1 + kk + (size_t)32 * HH);
                cp16(sdst[2] + so,             gW0 + kk);
                cp16(sdst[2] + so + 32 * ROWB, gW0 + kk + (size_t)32 * HH);
                cp16(sdst[3] + so,             gW1 + kk);
                cp16(sdst[3] + so + 32 * ROWB, gW1 + kk + (size_t)32 * HH);
                cp_commit();
                cp_wait1();
            } else {
                cp_wait0();
            }
            barg(mybar);

            const uint32_t sb = gbase + (uint32_t)cur * GSTAGE;
            #pragma unroll
            for (int kh = 0; kh < BK / 16; kh++) {
                const int kc = kh * 16;
                uint32_t ahi[2][4], alo[2][4];
                #pragma unroll
                for (int mt = 0; mt < 2; mt++) {
                    const uint32_t arow = (uint32_t)(wm * 32 + mt * 16 + a_row);
                    const uint32_t acol = (uint32_t)(kc + a_k) * 2;
                    ldsm4(ahi[mt], sb + (0 * BUFB) + arow * ROWB + acol);
                    ldsm4(alo[mt], sb + (1 * BUFB) + arow * ROWB + acol);
                }
                uint32_t bhi[8], blo[8];
                {
                    const uint32_t brow = (uint32_t)(wn * 32 + b_row);
                    const uint32_t bcol = (uint32_t)(kc + b_k) * 2;
                    ldsm4(bhi,     sb + (2 * BUFB) + brow * ROWB + bcol);
                    ldsm4(bhi + 4, sb + (2 * BUFB) + (brow + 16) * ROWB + bcol);
                    ldsm4(blo,     sb + (3 * BUFB) + brow * ROWB + bcol);
                    ldsm4(blo + 4, sb + (3 * BUFB) + (brow + 16) * ROWB + bcol);
                }
                #pragma unroll
                for (int mt = 0; mt < 2; mt++)
                    #pragma unroll
                    for (int nt = 0; nt < 4; nt++) {
                        mma_bf16(acc[mt][nt], ahi[mt], bhi + 2 * nt);
                        mma_bf16(acc[mt][nt], ahi[mt], blo + 2 * nt);
                        mma_bf16(acc[mt][nt], alo[mt], bhi + 2 * nt);
                    }
            }
            barg(mybar);
        }

        // ---- publish acc into own (now dead) pipeline region ----
        {
            float2* exg = (float2*)(smem + grp * GPIPE);
            #pragma unroll
            for (int mt = 0; mt < 2; mt++)
                #pragma unroll
                for (int nt = 0; nt < 4; nt++) {
                    const int p = (mt * 4 + nt) * 2;
                    exg[p * 128 + gtid]       = make_float2(acc[mt][nt][0], acc[mt][nt][1]);
                    exg[(p + 1) * 128 + gtid] = make_float2(acc[mt][nt][2], acc[mt][nt][3]);
                }
        }
        barall();

        // ---- distributed combine + epilogue (R7, verified) ----
        {
            const float x0 = x[(size_t)erow0 * TT + t];
            const float x1 = x[(size_t)(erow0 + 8) * TT + t];
            const int is_last = (t == TT - 1);

            #pragma unroll
            for (int p = 0; p < 4; p++) {
                const int pglob = grp * 4 + p;
                const int nt = ntBase + (p >> 1);
                const int eh = p & 1;
                const int j  = n0 + wn * 32 + nt * 8 + rid * 2;
                const int row = erow0 + eh * 8;
                const float xb = eh ? x1 : x0;

                float sx = 0.0f, sy = 0.0f;
                #pragma unroll
                for (int g = 0; g < 4; g++) {
                    float2 v = ((float2*)(smem + g * GPIPE))[pglob * 128 + gtid];
                    sx += v.x; sy += v.y;
                }
                const float v0 = tanhf(sx + xb * U[j]     + bh[j]);
                const float v1 = tanhf(sy + xb * U[j + 1] + bh[j + 1]);

                __nv_bfloat16 hh0 = __float2bfloat16(v0);
                __nv_bfloat16 hh1 = __float2bfloat16(v1);
                __nv_bfloat16 ll0 = __float2bfloat16(v0 - __bfloat162float(hh0));
                __nv_bfloat16 ll1 = __float2bfloat16(v1 - __bfloat162float(hh1));
                unsigned short s0 = *(unsigned short*)&hh0;
                unsigned short s1 = *(unsigned short*)&hh1;
                unsigned short w0 = *(unsigned short*)&ll0;
                unsigned short w1 = *(unsigned short*)&ll1;
                *(uint32_t*)(hhi_out + (size_t)row * HH + j) = (uint32_t)s0 | ((uint32_t)s1 << 16);
                *(uint32_t*)(hlo_out + (size_t)row * HH + j) = (uint32_t)w0 | ((uint32_t)w1 << 16);
                if (is_last) {
                    fout[(size_t)row * HH + j]     = v0;
                    fout[(size_t)row * HH + j + 1] = v1;
                }
            }
        }

        // ---- software global barrier (all 128 CTAs resident: one wave) ----
        if (t < TT - 1) {
            __threadfence();        // publish h stores to gpu scope
            barall();               // all threads of CTA done (incl. exchange reads)
            if (tid == 0) {
                atomicAdd(&g_bar, 1u);
                const unsigned tgt = (unsigned)(NCTA * (t + 1));
                while (*((volatile unsigned*)&g_bar) < tgt) { }
                __threadfence();    // acquire: other CTAs' h stores visible
            }
            barall();               // release all threads; also orders smem reuse
        }
    }
}

// ---------------------------------------------------------------------------
// Head: out[b,c] = sum_k h[b,k]*V[c,k] + bp[c]
// ---------------------------------------------------------------------------
__global__ __launch_bounds__(256)
void rnn_head_kernel(const float* __restrict__ h,
                     const float* __restrict__ V,
                     const float* __restrict__ bp,
                     float* __restrict__ out) {
    const int b = blockIdx.x;
    const int tid = threadIdx.x;
    __shared__ float red[256];

    float partial[CC];
    #pragma unroll
    for (int c = 0; c < CC; c++) partial[c] = 0.0f;

    const float* hrow = h + (size_t)b * HH;
    for (int k = tid; k < HH; k += 256) {
        float hv = hrow[k];
        #pragma unroll
        for (int c = 0; c < CC; c++)
            partial[c] = fmaf(hv, V[(size_t)c * HH + k], partial[c]);
    }

    for (int c = 0; c < CC; c++) {
        red[tid] = partial[c];
        __syncthreads();
        for (int s = 128; s > 0; s >>= 1) {
            if (tid < s) red[tid] += red[tid + s];
            __syncthreads();
        }
        if (tid == 0) out[(size_t)b * CC + c] = red[0] + bp[c];
        __syncthreads();
    }
}

// ---------------------------------------------------------------------------
// Host launch
// ---------------------------------------------------------------------------
extern "C" void kernel_launch(void* const* d_in, const int* in_sizes, int n_in,
                              void* d_out, int out_size) {
    const float* x  = (const float*)d_in[0];   // [B, T]
    const float* U  = (const float*)d_in[1];   // [H, 1]
    const float* W  = (const float*)d_in[2];   // [H, H]
    const float* V  = (const float*)d_in[3];   // [C, H]
    const float* bh = (const float*)d_in[4];   // [H]
    const float* bp = (const float*)d_in[5];   // [C]
    float* out = (float*)d_out;                // [B*H + B*C]

    cudaFuncSetAttribute(rnn_persist,
                         cudaFuncAttributeMaxDynamicSharedMemorySize, SMEM_TOTAL);

    // prep: split W into bf16 hi/lo, zero h0, reset barrier counter
    k_convert_w<<<(HH * HH + 255) / 256, 256>>>(W);
    k_init_h<<<(BB * HH + 255) / 256, 256>>>();

    // one persistent launch: 128 steps with internal global barrier
    dim3 grid(HH / BN, BB / BM);  // (32, 4) = 128 CTAs = one wave
    rnn_persist<<<grid, NTH, SMEM_TOTAL>>>(x, U, bh, out);

    // head on fp32 h_last (written into d_out by last step)
    rnn_head_kernel<<<BB, 256>>>(out, V, bp, out + (size_t)BB * HH);
}

// round 12
// speedup vs baseline: 1.3088x; 1.0650x over previous
#include <cuda_runtime.h>
#include <cuda_bf16.h>
#include <math.h>
#include <stdint.h>

// ---------------------------------------------------------------------------
// Problem constants
// ---------------------------------------------------------------------------
#define BB 256      // batch
#define TT 128      // timesteps
#define HH 2048     // hidden
#define CC 10       // classes

// ---------------------------------------------------------------------------
// R5 tiling (best measured): CTA 64x64 output, 512 threads = 4 K-groups x 4
// warps. Group g: K in [g*512,(g+1)*512), BK=32, 16 k-iters, 2-stage cp.async
// pipe, padded 80B rows. Warp tile 32x32 (2m x 2n per group).
// ---------------------------------------------------------------------------
#define BM 64
#define BN 64
#define BK 32
#define NGRP 4
#define KSPLIT (HH / NGRP)   // 512
#define NKT (KSPLIT / BK)    // 16
#define NTH 512

#define ROWB 80                          // 32 bf16 + 8 pad = 40 bf16 = 80 B
#define BUFB (64 * ROWB)                 // one 64-row buffer: 5120 B
#define GSTAGE (4 * BUFB)                // 4 buffers (Ahi,Alo,Whi,Wlo): 20480 B
#define GPIPE (2 * GSTAGE)               // 2 stages: 40960 B
#define SMEM_TOTAL (NGRP * GPIPE)        // 163840 B (exchange aliases pipeline)

// ---------------------------------------------------------------------------
// Device-global scratch (allocation-free)
// ---------------------------------------------------------------------------
__device__ __nv_bfloat16 g_whi[HH * HH];
__device__ __nv_bfloat16 g_wlo[HH * HH];
__device__ __nv_bfloat16 g_hhi[2][BB * HH];
__device__ __nv_bfloat16 g_hlo[2][BB * HH];

// ---------------------------------------------------------------------------
// PTX helpers (base-arch features only; nothing 'a'-gated)
// ---------------------------------------------------------------------------
__device__ __forceinline__ uint32_t smem_u32(const void* p) {
    uint32_t a;
    asm("{ .reg .u64 t; cvta.to.shared.u64 t, %1; cvt.u32.u64 %0, t; }"
        : "=r"(a) : "l"(p));
    return a;
}
__device__ __forceinline__ void cp16(uint32_t dst, const void* src) {
    asm volatile("cp.async.cg.shared.global [%0], [%1], 16;"
                 :: "r"(dst), "l"(src) : "memory");
}
__device__ __forceinline__ void cp_commit() {
    asm volatile("cp.async.commit_group;" ::: "memory");
}
__device__ __forceinline__ void cp_wait1() {
    asm volatile("cp.async.wait_group 1;" ::: "memory");
}
__device__ __forceinline__ void cp_wait0() {
    asm volatile("cp.async.wait_group 0;" ::: "memory");
}
__device__ __forceinline__ void barg(int id) {   // per-group barrier, 128 thr
    asm volatile("bar.sync %0, 128;" :: "r"(id) : "memory");
}
__device__ __forceinline__ void barall() {       // full CTA
    asm volatile("bar.sync 0, 512;" ::: "memory");
}
__device__ __forceinline__ void ldsm4(uint32_t* r, uint32_t addr) {
    asm volatile("ldmatrix.sync.aligned.m8n8.x4.shared.b16 {%0,%1,%2,%3}, [%4];"
                 : "=r"(r[0]), "=r"(r[1]), "=r"(r[2]), "=r"(r[3]) : "r"(addr));
}
__device__ __forceinline__ void mma_bf16(float* c, const uint32_t* a, const uint32_t* b) {
    asm volatile(
        "mma.sync.aligned.m16n8k16.row.col.f32.bf16.bf16.f32 "
        "{%0,%1,%2,%3}, {%4,%5,%6,%7}, {%8,%9}, {%0,%1,%2,%3};"
        : "+f"(c[0]), "+f"(c[1]), "+f"(c[2]), "+f"(c[3])
        : "r"(a[0]), "r"(a[1]), "r"(a[2]), "r"(a[3]), "r"(b[0]), "r"(b[1]));
}

// ---------------------------------------------------------------------------
// Prep kernels
// ---------------------------------------------------------------------------
__global__ void k_convert_w(const float* __restrict__ W) {
    int i = blockIdx.x * blockDim.x + threadIdx.x;
    if (i < HH * HH) {
        float w = W[i];
        __nv_bfloat16 hi = __float2bfloat16(w);
        g_whi[i] = hi;
        g_wlo[i] = __float2bfloat16(w - __bfloat162float(hi));
    }
}
__global__ void k_init_h() {
    int i = blockIdx.x * blockDim.x + threadIdx.x;
    if (i < BB * HH) {
        g_hhi[0][i] = __float2bfloat16(0.0f);
        g_hlo[0][i] = __float2bfloat16(0.0f);
    }
}

// ---------------------------------------------------------------------------
// One RNN step: D = (hhi+hlo) @ (Whi+Wlo)^T  (3-term bf16 split on HMMA)
// Mainloop identical to R5 (best measured). Epilogue distributed over all
// 512 threads via exchange buffers aliased into each group's dead pipeline.
// ---------------------------------------------------------------------------
__global__ __launch_bounds__(NTH, 1)
void rnn_step_hmma(const __nv_bfloat16* __restrict__ hhi_in,
                   const __nv_bfloat16* __restrict__ hlo_in,
                   const float* __restrict__ x,
                   const float* __restrict__ U,
                   const float* __restrict__ bh,
                   __nv_bfloat16* __restrict__ hhi_out,
                   __nv_bfloat16* __restrict__ hlo_out,
                   float* __restrict__ fout,
                   int t, int is_last) {
    extern __shared__ __align__(128) char smem[];
    const uint32_t sbase = smem_u32(smem);

    const int tid  = threadIdx.x;
    const int wid  = tid >> 5;
    const int lane = tid & 31;
    const int grp  = tid >> 7;           // 0..3
    const int gwid = wid & 3;
    const int gtid = tid & 127;
    const int n0 = blockIdx.x * BN;
    const int m0 = blockIdx.y * BM;

    const int wm = gwid & 1;
    const int wn = gwid >> 1;
    const int qid = lane >> 2;
    const int rid = lane & 3;

    const uint32_t gbase = sbase + (uint32_t)grp * GPIPE;
    const int kbase = grp * KSPLIT;

    // ---- cp.async mapping: per buffer rows r0, r0+32; 16B chunk ----
    const int r0   = gtid >> 2;          // 0..31
    const int cbf  = (gtid & 3) * 8;     // bf16 col offset
    const int cby  = (gtid & 3) * 16;    // byte col offset

    const __nv_bfloat16* gsrc[4];
    gsrc[0] = hhi_in + (size_t)(m0 + r0) * HH + kbase + cbf;
    gsrc[1] = hlo_in + (size_t)(m0 + r0) * HH + kbase + cbf;
    gsrc[2] = g_whi  + (size_t)(n0 + r0) * HH + kbase + cbf;
    gsrc[3] = g_wlo  + (size_t)(n0 + r0) * HH + kbase + cbf;

    uint32_t sdst[4];
    #pragma unroll
    for (int bf = 0; bf < 4; bf++)
        sdst[bf] = gbase + (uint32_t)(bf * BUFB + r0 * ROWB + cby);

    // ---- ldmatrix lane addressing ----
    const int a_row = (lane & 7) + 8 * ((lane >> 3) & 1);
    const int a_k   = 8 * (lane >> 4);
    const int b_row = ((lane >> 4) << 3) + (lane & 7);
    const int b_k   = ((lane >> 3) & 1) * 8;

    float acc[2][4][4];                  // [mt][n8 tile][elem]
    #pragma unroll
    for (int i = 0; i < 2; i++)
        #pragma unroll
        for (int j = 0; j < 4; j++)
            #pragma unroll
            for (int e = 0; e < 4; e++) acc[i][j][e] = 0.0f;

    // ---- prologue: stage 0 ----
    #pragma unroll
    for (int bf = 0; bf < 4; bf++) {
        cp16(sdst[bf],                 gsrc[bf]);
        cp16(sdst[bf] + 32 * ROWB,     gsrc[bf] + (size_t)32 * HH);
    }
    cp_commit();

    const int mybar = grp + 1;           // named barriers 1..4

    for (int kt = 0; kt < NKT; kt++) {
        const int cur = kt & 1;
        if (kt + 1 < NKT) {
            const uint32_t so = (uint32_t)((kt + 1) & 1) * GSTAGE;
            const int kk = (kt + 1) * BK;
            #pragma unroll
            for (int bf = 0; bf < 4; bf++) {
                cp16(sdst[bf] + so,             gsrc[bf] + kk);
                cp16(sdst[bf] + so + 32 * ROWB, gsrc[bf] + kk + (size_t)32 * HH);
            }
            cp_commit();
            cp_wait1();
        } else {
            cp_wait0();
        }
        barg(mybar);

        const uint32_t sb = gbase + (uint32_t)cur * GSTAGE;
        #pragma unroll
        for (int kh = 0; kh < BK / 16; kh++) {
            const int kc = kh * 16;
            uint32_t ahi[2][4], alo[2][4];
            #pragma unroll
            for (int mt = 0; mt < 2; mt++) {
                const uint32_t arow = (uint32_t)(wm * 32 + mt * 16 + a_row);
                const uint32_t acol = (uint32_t)(kc + a_k) * 2;
                ldsm4(ahi[mt], sb + (0 * BUFB) + arow * ROWB + acol);
                ldsm4(alo[mt], sb + (1 * BUFB) + arow * ROWB + acol);
            }
            uint32_t bhi[8], blo[8];
            {
                const uint32_t brow = (uint32_t)(wn * 32 + b_row);
                const uint32_t bcol = (uint32_t)(kc + b_k) * 2;
                ldsm4(bhi,     sb + (2 * BUFB) + brow * ROWB + bcol);
                ldsm4(bhi + 4, sb + (2 * BUFB) + (brow + 16) * ROWB + bcol);
                ldsm4(blo,     sb + (3 * BUFB) + brow * ROWB + bcol);
                ldsm4(blo + 4, sb + (3 * BUFB) + (brow + 16) * ROWB + bcol);
            }
            #pragma unroll
            for (int mt = 0; mt < 2; mt++)
                #pragma unroll
                for (int nt = 0; nt < 4; nt++) {
                    mma_bf16(acc[mt][nt], ahi[mt], bhi + 2 * nt);
                    mma_bf16(acc[mt][nt], ahi[mt], blo + 2 * nt);
                    mma_bf16(acc[mt][nt], alo[mt], bhi + 2 * nt);
                }
        }
        barg(mybar);
    }

    // ---- publish acc into own (now dead) pipeline region ----
    {
        float2* exg = (float2*)(smem + grp * GPIPE);
        #pragma unroll
        for (int mt = 0; mt < 2; mt++)
            #pragma unroll
            for (int nt = 0; nt < 4; nt++) {
                const int p = (mt * 4 + nt) * 2;
                exg[p * 128 + gtid]       = make_float2(acc[mt][nt][0], acc[mt][nt][1]);
                exg[(p + 1) * 128 + gtid] = make_float2(acc[mt][nt][2], acc[mt][nt][3]);
            }
    }
    barall();

    // ---- distributed combine + epilogue: each thread 4 pairs (8 outputs) ----
    {
        const int myMt   = grp >> 1;
        const int ntBase = (grp & 1) * 2;
        const int row0 = m0 + wm * 32 + myMt * 16 + qid;
        const float x0 = x[(size_t)row0 * TT + t];
        const float x1 = x[(size_t)(row0 + 8) * TT + t];

        #pragma unroll
        for (int p = 0; p < 4; p++) {
            const int pglob = grp * 4 + p;
            const int nt = ntBase + (p >> 1);
            const int eh = p & 1;
            const int j  = n0 + wn * 32 + nt * 8 + rid * 2;
            const int row = row0 + eh * 8;
            const float xb = eh ? x1 : x0;

            float sx = 0.0f, sy = 0.0f;
            #pragma unroll
            for (int g = 0; g < 4; g++) {
                float2 v = ((float2*)(smem + g * GPIPE))[pglob * 128 + gtid];
                sx += v.x; sy += v.y;
            }
            const float v0 = tanhf(sx + xb * U[j]     + bh[j]);
            const float v1 = tanhf(sy + xb * U[j + 1] + bh[j + 1]);

            __nv_bfloat16 hh0 = __float2bfloat16(v0);
            __nv_bfloat16 hh1 = __float2bfloat16(v1);
            __nv_bfloat16 ll0 = __float2bfloat16(v0 - __bfloat162float(hh0));
            __nv_bfloat16 ll1 = __float2bfloat16(v1 - __bfloat162float(hh1));
            unsigned short s0 = *(unsigned short*)&hh0;
            unsigned short s1 = *(unsigned short*)&hh1;
            unsigned short w0 = *(unsigned short*)&ll0;
            unsigned short w1 = *(unsigned short*)&ll1;
            *(uint32_t*)(hhi_out + (size_t)row * HH + j) = (uint32_t)s0 | ((uint32_t)s1 << 16);
            *(uint32_t*)(hlo_out + (size_t)row * HH + j) = (uint32_t)w0 | ((uint32_t)w1 << 16);
            if (is_last) {
                fout[(size_t)row * HH + j]     = v0;
                fout[(size_t)row * HH + j + 1] = v1;
            }
        }
    }
}

// ---------------------------------------------------------------------------
// Head: out[b,c] = sum_k h[b,k]*V[c,k] + bp[c]
// One block per batch row, one warp per class; shfl reduction.
// ---------------------------------------------------------------------------
__global__ __launch_bounds__(320)
void rnn_head_kernel(const float* __restrict__ h,
                     const float* __restrict__ V,
                     const float* __restrict__ bp,
                     float* __restrict__ out) {
    const int b = blockIdx.x;
    const int c = threadIdx.x >> 5;      // 0..9
    const int lane = threadIdx.x & 31;

    const float* hrow = h + (size_t)b * HH;
    const float* vrow = V + (size_t)c * HH;

    float s = 0.0f;
    #pragma unroll 16
    for (int k = lane; k < HH; k += 32)
        s = fmaf(hrow[k], vrow[k], s);

    #pragma unroll
    for (int o = 16; o > 0; o >>= 1)
        s += __shfl_down_sync(0xFFFFFFFF, s, o);

    if (lane == 0) out[(size_t)b * CC + c] = s + bp[c];
}

// ---------------------------------------------------------------------------
// Host launch
// ---------------------------------------------------------------------------
extern "C" void kernel_launch(void* const* d_in, const int* in_sizes, int n_in,
                              void* d_out, int out_size) {
    const float* x  = (const float*)d_in[0];   // [B, T]
    const float* U  = (const float*)d_in[1];   // [H, 1]
    const float* W  = (const float*)d_in[2];   // [H, H]
    const float* V  = (const float*)d_in[3];   // [C, H]
    const float* bh = (const float*)d_in[4];   // [H]
    const float* bp = (const float*)d_in[5];   // [C]
    float* out = (float*)d_out;                // [B*H + B*C]

    cudaFuncSetAttribute(rnn_step_hmma,
                         cudaFuncAttributeMaxDynamicSharedMemorySize, SMEM_TOTAL);

    void *p_hhi, *p_hlo;
    cudaGetSymbolAddress(&p_hhi, g_hhi);
    cudaGetSymbolAddress(&p_hlo, g_hlo);
    __nv_bfloat16* hhi = (__nv_bfloat16*)p_hhi;
    __nv_bfloat16* hlo = (__nv_bfloat16*)p_hlo;

    // prep: split W into bf16 hi/lo, zero h0
    k_convert_w<<<(HH * HH + 255) / 256, 256>>>(W);
    k_init_h<<<(BB * HH + 255) / 256, 256>>>();

    // 128 sequential steps, ping-pong bf16 hidden state
    dim3 grid(HH / BN, BB / BM);  // (32, 4) = 128 CTAs
    for (int t = 0; t < TT; t++) {
        const int inb  = t & 1;
        const int outb = inb ^ 1;
        rnn_step_hmma<<<grid, NTH, SMEM_TOTAL>>>(
            hhi + (size_t)inb * BB * HH,
            hlo + (size_t)inb * BB * HH,
            x, U, bh,
            hhi + (size_t)outb * BB * HH,
            hlo + (size_t)outb * BB * HH,
            out, t, (t == TT - 1) ? 1 : 0);
    }

    // head on fp32 h_last (written into d_out by last step)
    rnn_head_kernel<<<BB, 320>>>(out, V, bp, out + (size_t)BB * HH);
}

// round 13
// speedup vs baseline: 1.7438x; 1.3324x over previous
#include <cuda_runtime.h>
#include <cuda_fp16.h>
#include <math.h>
#include <stdint.h>

// ---------------------------------------------------------------------------
// Problem constants
// ---------------------------------------------------------------------------
#define BB 256      // batch
#define TT 128      // timesteps
#define HH 2048     // hidden
#define CC 10       // classes

// ---------------------------------------------------------------------------
// R5/R12 tiling (best measured): CTA 64x64 output, 512 threads = 4 K-groups
// x 4 warps. Group g: K in [g*512,(g+1)*512), BK=32, 16 k-iters, 2-stage
// cp.async pipe, padded 80B rows. Warp tile 32x32 (2m x 2n per group).
// NEW (R13): fp16 W-split 2-term: D = h(fp16) @ (Whi + Wlo)^T, W pair exact.
// 3 buffers per stage (A, Whi, Wlo); 2 MMA terms instead of 3.
// ---------------------------------------------------------------------------
#define BM 64
#define BN 64
#define BK 32
#define NGRP 4
#define KSPLIT (HH / NGRP)   // 512
#define NKT (KSPLIT / BK)    // 16
#define NTH 512

#define ROWB 80                          // 32 fp16 + 8 pad = 40 halves = 80 B
#define BUFB (64 * ROWB)                 // one 64-row buffer: 5120 B
#define GSTAGE (3 * BUFB)                // 3 buffers (A,Whi,Wlo): 15360 B
// GPIPE padded to 32768 so the per-group exchange region (32 KB) fits when
// aliased over the dead pipeline after the mainloop.
#define GPIPE 32768                      // >= 2*GSTAGE (30720)
#define SMEM_TOTAL (NGRP * GPIPE)        // 131072 B

// ---------------------------------------------------------------------------
// Device-global scratch (allocation-free)
// ---------------------------------------------------------------------------
__device__ __half g_whi[HH * HH];
__device__ __half g_wlo[HH * HH];
__device__ __half g_h[2][BB * HH];

// ---------------------------------------------------------------------------
// PTX helpers (base-arch features only; nothing 'a'-gated)
// ---------------------------------------------------------------------------
__device__ __forceinline__ uint32_t smem_u32(const void* p) {
    uint32_t a;
    asm("{ .reg .u64 t; cvta.to.shared.u64 t, %1; cvt.u32.u64 %0, t; }"
        : "=r"(a) : "l"(p));
    return a;
}
__device__ __forceinline__ void cp16(uint32_t dst, const void* src) {
    asm volatile("cp.async.cg.shared.global [%0], [%1], 16;"
                 :: "r"(dst), "l"(src) : "memory");
}
__device__ __forceinline__ void cp_commit() {
    asm volatile("cp.async.commit_group;" ::: "memory");
}
__device__ __forceinline__ void cp_wait1() {
    asm volatile("cp.async.wait_group 1;" ::: "memory");
}
__device__ __forceinline__ void cp_wait0() {
    asm volatile("cp.async.wait_group 0;" ::: "memory");
}
__device__ __forceinline__ void barg(int id) {   // per-group barrier, 128 thr
    asm volatile("bar.sync %0, 128;" :: "r"(id) : "memory");
}
__device__ __forceinline__ void barall() {       // full CTA
    asm volatile("bar.sync 0, 512;" ::: "memory");
}
__device__ __forceinline__ void ldsm4(uint32_t* r, uint32_t addr) {
    asm volatile("ldmatrix.sync.aligned.m8n8.x4.shared.b16 {%0,%1,%2,%3}, [%4];"
                 : "=r"(r[0]), "=r"(r[1]), "=r"(r[2]), "=r"(r[3]) : "r"(addr));
}
__device__ __forceinline__ void mma_fp16(float* c, const uint32_t* a, const uint32_t* b) {
    asm volatile(
        "mma.sync.aligned.m16n8k16.row.col.f32.f16.f16.f32 "
        "{%0,%1,%2,%3}, {%4,%5,%6,%7}, {%8,%9}, {%0,%1,%2,%3};"
        : "+f"(c[0]), "+f"(c[1]), "+f"(c[2]), "+f"(c[3])
        : "r"(a[0]), "r"(a[1]), "r"(a[2]), "r"(a[3]), "r"(b[0]), "r"(b[1]));
}

// ---------------------------------------------------------------------------
// Prep kernels
// ---------------------------------------------------------------------------
__global__ void k_convert_w(const float* __restrict__ W) {
    int i = blockIdx.x * blockDim.x + threadIdx.x;
    if (i < HH * HH) {
        float w = W[i];
        __half hi = __float2half_rn(w);
        g_whi[i] = hi;
        g_wlo[i] = __float2half_rn(w - __half2float(hi));
    }
}
__global__ void k_init_h() {
    int i = blockIdx.x * blockDim.x + threadIdx.x;
    if (i < BB * HH) g_h[0][i] = __float2half_rn(0.0f);
}

// ---------------------------------------------------------------------------
// One RNN step: D = h @ (Whi + Wlo)^T  (fp16 W-split 2-term on HMMA)
// Mainloop rhythm identical to R12. Epilogue distributed over all 512
// threads via exchange buffers aliased into each group's dead pipeline.
// ---------------------------------------------------------------------------
__global__ __launch_bounds__(NTH, 1)
void rnn_step_hmma(const __half* __restrict__ h_in,
                   const float* __restrict__ x,
                   const float* __restrict__ U,
                   const float* __restrict__ bh,
                   __half* __restrict__ h_out,
                   float* __restrict__ fout,
                   int t, int is_last) {
    extern __shared__ __align__(128) char smem[];
    const uint32_t sbase = smem_u32(smem);

    const int tid  = threadIdx.x;
    const int wid  = tid >> 5;
    const int lane = tid & 31;
    const int grp  = tid >> 7;           // 0..3
    const int gwid = wid & 3;
    const int gtid = tid & 127;
    const int n0 = blockIdx.x * BN;
    const int m0 = blockIdx.y * BM;

    const int wm = gwid & 1;
    const int wn = gwid >> 1;
    const int qid = lane >> 2;
    const int rid = lane & 3;

    const uint32_t gbase = sbase + (uint32_t)grp * GPIPE;
    const int kbase = grp * KSPLIT;

    // ---- cp.async mapping: per buffer rows r0, r0+32; 16B chunk ----
    const int r0   = gtid >> 2;          // 0..31
    const int cbf  = (gtid & 3) * 8;     // fp16 col offset
    const int cby  = (gtid & 3) * 16;    // byte col offset

    const __half* gsrc[3];
    gsrc[0] = h_in  + (size_t)(m0 + r0) * HH + kbase + cbf;
    gsrc[1] = g_whi + (size_t)(n0 + r0) * HH + kbase + cbf;
    gsrc[2] = g_wlo + (size_t)(n0 + r0) * HH + kbase + cbf;

    uint32_t sdst[3];
    #pragma unroll
    for (int bf = 0; bf < 3; bf++)
        sdst[bf] = gbase + (uint32_t)(bf * BUFB + r0 * ROWB + cby);

    // ---- ldmatrix lane addressing ----
    const int a_row = (lane & 7) + 8 * ((lane >> 3) & 1);
    const int a_k   = 8 * (lane >> 4);
    const int b_row = ((lane >> 4) << 3) + (lane & 7);
    const int b_k   = ((lane >> 3) & 1) * 8;

    float acc[2][4][4];                  // [mt][n8 tile][elem]
    #pragma unroll
    for (int i = 0; i < 2; i++)
        #pragma unroll
        for (int j = 0; j < 4; j++)
            #pragma unroll
            for (int e = 0; e < 4; e++) acc[i][j][e] = 0.0f;

    // ---- prologue: stage 0 ----
    #pragma unroll
    for (int bf = 0; bf < 3; bf++) {
        cp16(sdst[bf],             gsrc[bf]);
        cp16(sdst[bf] + 32 * ROWB, gsrc[bf] + (size_t)32 * HH);
    }
    cp_commit();

    const int mybar = grp + 1;           // named barriers 1..4

    for (int kt = 0; kt < NKT; kt++) {
        const int cur = kt & 1;
        if (kt + 1 < NKT) {
            const uint32_t so = (uint32_t)((kt + 1) & 1) * GSTAGE;
            const int kk = (kt + 1) * BK;
            #pragma unroll
            for (int bf = 0; bf < 3; bf++) {
                cp16(sdst[bf] + so,             gsrc[bf] + kk);
                cp16(sdst[bf] + so + 32 * ROWB, gsrc[bf] + kk + (size_t)32 * HH);
            }
            cp_commit();
            cp_wait1();
        } else {
            cp_wait0();
        }
        barg(mybar);

        const uint32_t sb = gbase + (uint32_t)cur * GSTAGE;
        #pragma unroll
        for (int kh = 0; kh < BK / 16; kh++) {
            const int kc = kh * 16;
            uint32_t afr[2][4];
            #pragma unroll
            for (int mt = 0; mt < 2; mt++) {
                const uint32_t arow = (uint32_t)(wm * 32 + mt * 16 + a_row);
                const uint32_t acol = (uint32_t)(kc + a_k) * 2;
                ldsm4(afr[mt], sb + (0 * BUFB) + arow * ROWB + acol);
            }
            uint32_t bhi[8], blo[8];
            {
                const uint32_t brow = (uint32_t)(wn * 32 + b_row);
                const uint32_t bcol = (uint32_t)(kc + b_k) * 2;
                ldsm4(bhi,     sb + (1 * BUFB) + brow * ROWB + bcol);
                ldsm4(bhi + 4, sb + (1 * BUFB) + (brow + 16) * ROWB + bcol);
                ldsm4(blo,     sb + (2 * BUFB) + brow * ROWB + bcol);
                ldsm4(blo + 4, sb + (2 * BUFB) + (brow + 16) * ROWB + bcol);
            }
            #pragma unroll
            for (int mt = 0; mt < 2; mt++)
                #pragma unroll
                for (int nt = 0; nt < 4; nt++) {
                    mma_fp16(acc[mt][nt], afr[mt], bhi + 2 * nt);
                    mma_fp16(acc[mt][nt], afr[mt], blo + 2 * nt);
                }
        }
        barg(mybar);
    }

    // ---- publish acc into own (now dead) pipeline region ----
    {
        float2* exg = (float2*)(smem + grp * GPIPE);
        #pragma unroll
        for (int mt = 0; mt < 2; mt++)
            #pragma unroll
            for (int nt = 0; nt < 4; nt++) {
                const int p = (mt * 4 + nt) * 2;
                exg[p * 128 + gtid]       = make_float2(acc[mt][nt][0], acc[mt][nt][1]);
                exg[(p + 1) * 128 + gtid] = make_float2(acc[mt][nt][2], acc[mt][nt][3]);
            }
    }
    barall();

    // ---- distributed combine + epilogue: each thread 4 pairs (8 outputs) ----
    {
        const int myMt   = grp >> 1;
        const int ntBase = (grp & 1) * 2;
        const int row0 = m0 + wm * 32 + myMt * 16 + qid;
        const float x0 = x[(size_t)row0 * TT + t];
        const float x1 = x[(size_t)(row0 + 8) * TT + t];

        #pragma unroll
        for (int p = 0; p < 4; p++) {
            const int pglob = grp * 4 + p;
            const int nt = ntBase + (p >> 1);
            const int eh = p & 1;
            const int j  = n0 + wn * 32 + nt * 8 + rid * 2;
            const int row = row0 + eh * 8;
            const float xb = eh ? x1 : x0;

            float sx = 0.0f, sy = 0.0f;
            #pragma unroll
            for (int g = 0; g < 4; g++) {
                float2 v = ((float2*)(smem + g * GPIPE))[pglob * 128 + gtid];
                sx += v.x; sy += v.y;
            }
            const float v0 = tanhf(sx + xb * U[j]     + bh[j]);
            const float v1 = tanhf(sy + xb * U[j + 1] + bh[j + 1]);

            __half hh0 = __float2half_rn(v0);
            __half hh1 = __float2half_rn(v1);
            unsigned short s0 = *(unsigned short*)&hh0;
            unsigned short s1 = *(unsigned short*)&hh1;
            *(uint32_t*)(h_out + (size_t)row * HH + j) = (uint32_t)s0 | ((uint32_t)s1 << 16);
            if (is_last) {
                fout[(size_t)row * HH + j]     = v0;
                fout[(size_t)row * HH + j + 1] = v1;
            }
        }
    }
}

// ---------------------------------------------------------------------------
// Head: out[b,c] = sum_k h[b,k]*V[c,k] + bp[c]
// One block per batch row, one warp per class; shfl reduction.
// ---------------------------------------------------------------------------
__global__ __launch_bounds__(320)
void rnn_head_kernel(const float* __restrict__ h,
                     const float* __restrict__ V,
                     const float* __restrict__ bp,
                     float* __restrict__ out) {
    const int b = blockIdx.x;
    const int c = threadIdx.x >> 5;      // 0..9
    const int lane = threadIdx.x & 31;

    const float* hrow = h + (size_t)b * HH;
    const float* vrow = V + (size_t)c * HH;

    float s = 0.0f;
    #pragma unroll 16
    for (int k = lane; k < HH; k += 32)
        s = fmaf(hrow[k], vrow[k], s);

    #pragma unroll
    for (int o = 16; o > 0; o >>= 1)
        s += __shfl_down_sync(0xFFFFFFFF, s, o);

    if (lane == 0) out[(size_t)b * CC + c] = s + bp[c];
}

// ---------------------------------------------------------------------------
// Host launch
// ---------------------------------------------------------------------------
extern "C" void kernel_launch(void* const* d_in, const int* in_sizes, int n_in,
                              void* d_out, int out_size) {
    const float* x  = (const float*)d_in[0];   // [B, T]
    const float* U  = (const float*)d_in[1];   // [H, 1]
    const float* W  = (const float*)d_in[2];   // [H, H]
    const float* V  = (const float*)d_in[3];   // [C, H]
    const float* bh = (const float*)d_in[4];   // [H]
    const float* bp = (const float*)d_in[5];   // [C]
    float* out = (float*)d_out;                // [B*H + B*C]

    cudaFuncSetAttribute(rnn_step_hmma,
                         cudaFuncAttributeMaxDynamicSharedMemorySize, SMEM_TOTAL);

    void* p_h;
    cudaGetSymbolAddress(&p_h, g_h);
    __half* hbuf = (__half*)p_h;

    // prep: split W into fp16 hi/lo (exact pair), zero h0
    k_convert_w<<<(HH * HH + 255) / 256, 256>>>(W);
    k_init_h<<<(BB * HH + 255) / 256, 256>>>();

    // 128 sequential steps, ping-pong fp16 hidden state
    dim3 grid(HH / BN, BB / BM);  // (32, 4) = 128 CTAs
    for (int t = 0; t < TT; t++) {
        const int inb  = t & 1;
        const int outb = inb ^ 1;
        rnn_step_hmma<<<grid, NTH, SMEM_TOTAL>>>(
            hbuf + (size_t)inb * BB * HH,
            x, U, bh,
            hbuf + (size_t)outb * BB * HH,
            out, t, (t == TT - 1) ? 1 : 0);
    }

    // head on fp32 h_last (written into d_out by last step)
    rnn_head_kernel<<<BB, 320>>>(out, V, bp, out + (size_t)BB * HH);
}

// round 14
// speedup vs baseline: 2.4644x; 1.4132x over previous
#include <cuda_runtime.h>
#include <cuda_fp16.h>
#include <math.h>
#include <stdint.h>

// ---------------------------------------------------------------------------
// Problem constants
// ---------------------------------------------------------------------------
#define BB 256      // batch
#define TT 128      // timesteps
#define HH 2048     // hidden
#define CC 10       // classes

// ---------------------------------------------------------------------------
// R13 scheme (fp16 W-split 2-term: D = h @ (Whi+Wlo)^T), with BK 32->64:
// CTA 64x64, 512 threads = 4 K-groups x 4 warps; group g: K in [g*512,..),
// BK=64, 8 k-iters, 2-stage cp.async pipe, 128B swizzled rows (no pad).
// Accumulation order identical to R13 (bit-identical numerics).
// ---------------------------------------------------------------------------
#define BM 64
#define BN 64
#define BK 64
#define NGRP 4
#define KSPLIT (HH / NGRP)   // 512
#define NKT (KSPLIT / BK)    // 8
#define NTH 512

#define ROWB 128                         // 64 fp16, no pad (XOR swizzled)
#define BUFB (64 * ROWB)                 // one 64-row buffer: 8192 B
#define GSTAGE (3 * BUFB)                // 3 buffers (A,Whi,Wlo): 24576 B
#define GPIPE (2 * GSTAGE)               // 49152 B (also >= 32KB exchange)
#define SMEM_TOTAL (NGRP * GPIPE)        // 196608 B

// ---------------------------------------------------------------------------
// Device-global scratch (allocation-free)
// ---------------------------------------------------------------------------
__device__ __half g_whi[HH * HH];
__device__ __half g_wlo[HH * HH];
__device__ __half g_h[2][BB * HH];

// ---------------------------------------------------------------------------
// PTX helpers (base-arch features only; nothing 'a'-gated)
// ---------------------------------------------------------------------------
__device__ __forceinline__ uint32_t smem_u32(const void* p) {
    uint32_t a;
    asm("{ .reg .u64 t; cvta.to.shared.u64 t, %1; cvt.u32.u64 %0, t; }"
        : "=r"(a) : "l"(p));
    return a;
}
__device__ __forceinline__ void cp16(uint32_t dst, const void* src) {
    asm volatile("cp.async.cg.shared.global [%0], [%1], 16;"
                 :: "r"(dst), "l"(src) : "memory");
}
__device__ __forceinline__ void cp_commit() {
    asm volatile("cp.async.commit_group;" ::: "memory");
}
__device__ __forceinline__ void cp_wait1() {
    asm volatile("cp.async.wait_group 1;" ::: "memory");
}
__device__ __forceinline__ void cp_wait0() {
    asm volatile("cp.async.wait_group 0;" ::: "memory");
}
__device__ __forceinline__ void barg(int id) {   // per-group barrier, 128 thr
    asm volatile("bar.sync %0, 128;" :: "r"(id) : "memory");
}
__device__ __forceinline__ void barall() {       // full CTA
    asm volatile("bar.sync 0, 512;" ::: "memory");
}
__device__ __forceinline__ void ldsm4(uint32_t* r, uint32_t addr) {
    asm volatile("ldmatrix.sync.aligned.m8n8.x4.shared.b16 {%0,%1,%2,%3}, [%4];"
                 : "=r"(r[0]), "=r"(r[1]), "=r"(r[2]), "=r"(r[3]) : "r"(addr));
}
__device__ __forceinline__ void mma_fp16(float* c, const uint32_t* a, const uint32_t* b) {
    asm volatile(
        "mma.sync.aligned.m16n8k16.row.col.f32.f16.f16.f32 "
        "{%0,%1,%2,%3}, {%4,%5,%6,%7}, {%8,%9}, {%0,%1,%2,%3};"
        : "+f"(c[0]), "+f"(c[1]), "+f"(c[2]), "+f"(c[3])
        : "r"(a[0]), "r"(a[1]), "r"(a[2]), "r"(a[3]), "r"(b[0]), "r"(b[1]));
}

// ---------------------------------------------------------------------------
// Prep kernels
// ---------------------------------------------------------------------------
__global__ void k_convert_w(const float* __restrict__ W) {
    int i = blockIdx.x * blockDim.x + threadIdx.x;
    if (i < HH * HH) {
        float w = W[i];
        __half hi = __float2half_rn(w);
        g_whi[i] = hi;
        g_wlo[i] = __float2half_rn(w - __half2float(hi));
    }
}
__global__ void k_init_h() {
    int i = blockIdx.x * blockDim.x + threadIdx.x;
    if (i < BB * HH) g_h[0][i] = __float2half_rn(0.0f);
}

// ---------------------------------------------------------------------------
// One RNN step: D = h @ (Whi + Wlo)^T  (fp16 W-split 2-term on HMMA)
// BK=64, 8 k-iters, swizzled 128B rows. Accumulation order == R13.
// ---------------------------------------------------------------------------
__global__ __launch_bounds__(NTH, 1)
void rnn_step_hmma(const __half* __restrict__ h_in,
                   const float* __restrict__ x,
                   const float* __restrict__ U,
                   const float* __restrict__ bh,
                   __half* __restrict__ h_out,
                   float* __restrict__ fout,
                   int t, int is_last) {
    extern __shared__ __align__(128) char smem[];
    const uint32_t sbase = smem_u32(smem);

    const int tid  = threadIdx.x;
    const int wid  = tid >> 5;
    const int lane = tid & 31;
    const int grp  = tid >> 7;           // 0..3
    const int gwid = wid & 3;
    const int gtid = tid & 127;
    const int n0 = blockIdx.x * BN;
    const int m0 = blockIdx.y * BM;

    const int wm = gwid & 1;
    const int wn = gwid >> 1;
    const int qid = lane >> 2;
    const int rid = lane & 3;

    const uint32_t gbase = sbase + (uint32_t)grp * GPIPE;
    const int kbase = grp * KSPLIT;

    // ---- cp.async mapping: 4 chunks/thread/buffer (64 rows x 8 chunks) ----
    // q in {gtid, gtid+128, gtid+256, gtid+384}: row=q>>3, chunk c=q&7.
    int srcoff[4];       // element offset into global row-major tile
    uint32_t dstoff[4];  // byte offset into swizzled smem buffer
    #pragma unroll
    for (int i = 0; i < 4; i++) {
        const int q = gtid + i * 128;
        const int row = q >> 3;
        const int c = q & 7;
        srcoff[i] = row * HH + c * 8;
        dstoff[i] = (uint32_t)(row * ROWB + ((c ^ (row & 7)) << 4));
    }

    const __half* gsrc[3];
    gsrc[0] = h_in  + (size_t)m0 * HH + kbase;
    gsrc[1] = g_whi + (size_t)n0 * HH + kbase;
    gsrc[2] = g_wlo + (size_t)n0 * HH + kbase;

    // ---- ldmatrix lane addressing ----
    const int a_row = (lane & 7) + 8 * ((lane >> 3) & 1);
    const int a_c   = lane >> 4;               // chunk sub-index (0..1)
    const int b_row = ((lane >> 4) << 3) + (lane & 7);
    const int b_c   = (lane >> 3) & 1;

    // per-tile row constants
    const int arow0 = wm * 32 + a_row;         // mt=0 row; mt=1 adds 16
    const int brow0 = wn * 32 + b_row;         // tile0 row; tile1 adds 16

    float acc[2][4][4];                        // [mt][n8 tile][elem]
    #pragma unroll
    for (int i = 0; i < 2; i++)
        #pragma unroll
        for (int j = 0; j < 4; j++)
            #pragma unroll
            for (int e = 0; e < 4; e++) acc[i][j][e] = 0.0f;

    // ---- prologue: stage 0 ----
    #pragma unroll
    for (int bf = 0; bf < 3; bf++) {
        const uint32_t db = gbase + (uint32_t)(bf * BUFB);
        #pragma unroll
        for (int i = 0; i < 4; i++)
            cp16(db + dstoff[i], gsrc[bf] + srcoff[i]);
    }
    cp_commit();

    const int mybar = grp + 1;                 // named barriers 1..4

    for (int kt = 0; kt < NKT; kt++) {
        const int cur = kt & 1;
        if (kt + 1 < NKT) {
            const uint32_t so = (uint32_t)((kt + 1) & 1) * GSTAGE;
            const int kk = (kt + 1) * BK;
            #pragma unroll
            for (int bf = 0; bf < 3; bf++) {
                const uint32_t db = gbase + so + (uint32_t)(bf * BUFB);
                #pragma unroll
                for (int i = 0; i < 4; i++)
                    cp16(db + dstoff[i], gsrc[bf] + kk + srcoff[i]);
            }
            cp_commit();
            cp_wait1();
        } else {
            cp_wait0();
        }
        barg(mybar);

        const uint32_t sb = gbase + (uint32_t)cur * GSTAGE;
        #pragma unroll
        for (int kh = 0; kh < BK / 16; kh++) {
            // A fragments: 2 m16 tiles
            uint32_t afr[2][4];
            #pragma unroll
            for (int mt = 0; mt < 2; mt++) {
                const int ar = arow0 + mt * 16;
                const int ac = (kh * 2 + a_c) ^ (ar & 7);
                ldsm4(afr[mt], sb + (0 * BUFB) + (uint32_t)(ar * ROWB + (ac << 4)));
            }
            // B fragments: Whi + Wlo, 2 row-tiles each
            uint32_t bhi[8], blo[8];
            {
                const int br0 = brow0, br1 = brow0 + 16;
                const int bc0 = (kh * 2 + b_c) ^ (br0 & 7);
                const int bc1 = (kh * 2 + b_c) ^ (br1 & 7);
                ldsm4(bhi,     sb + (1 * BUFB) + (uint32_t)(br0 * ROWB + (bc0 << 4)));
                ldsm4(bhi + 4, sb + (1 * BUFB) + (uint32_t)(br1 * ROWB + (bc1 << 4)));
                ldsm4(blo,     sb + (2 * BUFB) + (uint32_t)(br0 * ROWB + (bc0 << 4)));
                ldsm4(blo + 4, sb + (2 * BUFB) + (uint32_t)(br1 * ROWB + (bc1 << 4)));
            }
            #pragma unroll
            for (int mt = 0; mt < 2; mt++)
                #pragma unroll
                for (int nt = 0; nt < 4; nt++) {
                    mma_fp16(acc[mt][nt], afr[mt], bhi + 2 * nt);
                    mma_fp16(acc[mt][nt], afr[mt], blo + 2 * nt);
                }
        }
        barg(mybar);
    }

    // ---- publish acc into own (now dead) pipeline region ----
    {
        float2* exg = (float2*)(smem + grp * GPIPE);
        #pragma unroll
        for (int mt = 0; mt < 2; mt++)
            #pragma unroll
            for (int nt = 0; nt < 4; nt++) {
                const int p = (mt * 4 + nt) * 2;
                exg[p * 128 + gtid]       = make_float2(acc[mt][nt][0], acc[mt][nt][1]);
                exg[(p + 1) * 128 + gtid] = make_float2(acc[mt][nt][2], acc[mt][nt][3]);
            }
    }
    barall();

    // ---- distributed combine + epilogue: each thread 4 pairs (8 outputs) ----
    {
        const int myMt   = grp >> 1;
        const int ntBase = (grp & 1) * 2;
        const int row0 = m0 + wm * 32 + myMt * 16 + qid;
        const float x0 = x[(size_t)row0 * TT + t];
        const float x1 = x[(size_t)(row0 + 8) * TT + t];

        #pragma unroll
        for (int p = 0; p < 4; p++) {
            const int pglob = grp * 4 + p;
            const int nt = ntBase + (p >> 1);
            const int eh = p & 1;
            const int j  = n0 + wn * 32 + nt * 8 + rid * 2;
            const int row = row0 + eh * 8;
            const float xb = eh ? x1 : x0;

            float sx = 0.0f, sy = 0.0f;
            #pragma unroll
            for (int g = 0; g < 4; g++) {
                float2 v = ((float2*)(smem + g * GPIPE))[pglob * 128 + gtid];
                sx += v.x; sy += v.y;
            }
            const float v0 = tanhf(sx + xb * U[j]     + bh[j]);
            const float v1 = tanhf(sy + xb * U[j + 1] + bh[j + 1]);

            __half hh0 = __float2half_rn(v0);
            __half hh1 = __float2half_rn(v1);
            unsigned short s0 = *(unsigned short*)&hh0;
            unsigned short s1 = *(unsigned short*)&hh1;
            *(uint32_t*)(h_out + (size_t)row * HH + j) = (uint32_t)s0 | ((uint32_t)s1 << 16);
            if (is_last) {
                fout[(size_t)row * HH + j]     = v0;
                fout[(size_t)row * HH + j + 1] = v1;
            }
        }
    }
}

// ---------------------------------------------------------------------------
// Head: out[b,c] = sum_k h[b,k]*V[c,k] + bp[c]
// One block per batch row, one warp per class; shfl reduction.
// ---------------------------------------------------------------------------
__global__ __launch_bounds__(320)
void rnn_head_kernel(const float* __restrict__ h,
                     const float* __restrict__ V,
                     const float* __restrict__ bp,
                     float* __restrict__ out) {
    const int b = blockIdx.x;
    const int c = threadIdx.x >> 5;      // 0..9
    const int lane = threadIdx.x & 31;

    const float* hrow = h + (size_t)b * HH;
    const float* vrow = V + (size_t)c * HH;

    float s = 0.0f;
    #pragma unroll 16
    for (int k = lane; k < HH; k += 32)
        s = fmaf(hrow[k], vrow[k], s);

    #pragma unroll
    for (int o = 16; o > 0; o >>= 1)
        s += __shfl_down_sync(0xFFFFFFFF, s, o);

    if (lane == 0) out[(size_t)b * CC + c] = s + bp[c];
}

// ---------------------------------------------------------------------------
// Host launch
// ---------------------------------------------------------------------------
extern "C" void kernel_launch(void* const* d_in, const int* in_sizes, int n_in,
                              void* d_out, int out_size) {
    const float* x  = (const float*)d_in[0];   // [B, T]
    const float* U  = (const float*)d_in[1];   // [H, 1]
    const float* W  = (const float*)d_in[2];   // [H, H]
    const float* V  = (const float*)d_in[3];   // [C, H]
    const float* bh = (const float*)d_in[4];   // [H]
    const float* bp = (const float*)d_in[5];   // [C]
    float* out = (float*)d_out;                // [B*H + B*C]

    cudaFuncSetAttribute(rnn_step_hmma,
                         cudaFuncAttributeMaxDynamicSharedMemorySize, SMEM_TOTAL);

    void* p_h;
    cudaGetSymbolAddress(&p_h, g_h);
    __half* hbuf = (__half*)p_h;

    // prep: split W into fp16 hi/lo (exact pair), zero h0
    k_convert_w<<<(HH * HH + 255) / 256, 256>>>(W);
    k_init_h<<<(BB * HH + 255) / 256, 256>>>();

    // 128 sequential steps, ping-pong fp16 hidden state
    dim3 grid(HH / BN, BB / BM);  // (32, 4) = 128 CTAs
    for (int t = 0; t < TT; t++) {
        const int inb  = t & 1;
        const int outb = inb ^ 1;
        rnn_step_hmma<<<grid, NTH, SMEM_TOTAL>>>(
            hbuf + (size_t)inb * BB * HH,
            x, U, bh,
            hbuf + (size_t)outb * BB * HH,
            out, t, (t == TT - 1) ? 1 : 0);
    }

    // head on fp32 h_last (written into d_out by last step)
    rnn_head_kernel<<<BB, 320>>>(out, V, bp, out + (size_t)BB * HH);
}

// round 16
// speedup vs baseline: 2.4904x; 1.0105x over previous
#include <cuda_runtime.h>
#include <cuda_fp16.h>
#include <math.h>
#include <stdint.h>

// ---------------------------------------------------------------------------
// Problem constants
// ---------------------------------------------------------------------------
#define BB 256      // batch
#define TT 128      // timesteps
#define HH 2048     // hidden
#define CC 10       // classes

// ---------------------------------------------------------------------------
// R14 scheme (fp16 W-split 2-term, BK=64, swizzled 128B rows) + R15 change:
// per-group startup phase stagger (grp * 200 cyc) to de-convoy the 4 groups
// so crossbar (ldsm) bursts of one group overlap tensor bursts of another
// on each SMSP. No arithmetic change: numerics bit-identical to R14.
// ---------------------------------------------------------------------------
#define BM 64
#define BN 64
#define BK 64
#define NGRP 4
#define KSPLIT (HH / NGRP)   // 512
#define NKT (KSPLIT / BK)    // 8
#define NTH 512

#define ROWB 128                         // 64 fp16, no pad (XOR swizzled)
#define BUFB (64 * ROWB)                 // one 64-row buffer: 8192 B
#define GSTAGE (3 * BUFB)                // 3 buffers (A,Whi,Wlo): 24576 B
#define GPIPE (2 * GSTAGE)               // 49152 B (also >= 32KB exchange)
#define SMEM_TOTAL (NGRP * GPIPE)        // 196608 B

#define SKEW_CYC 200                     // per-group phase offset

// ---------------------------------------------------------------------------
// Device-global scratch (allocation-free)
// ---------------------------------------------------------------------------
__device__ __half g_whi[HH * HH];
__device__ __half g_wlo[HH * HH];
__device__ __half g_h[2][BB * HH];

// ---------------------------------------------------------------------------
// PTX helpers (base-arch features only; nothing 'a'-gated)
// ---------------------------------------------------------------------------
__device__ __forceinline__ uint32_t smem_u32(const void* p) {
    uint32_t a;
    asm("{ .reg .u64 t; cvta.to.shared.u64 t, %1; cvt.u32.u64 %0, t; }"
        : "=r"(a) : "l"(p));
    return a;
}
__device__ __forceinline__ void cp16(uint32_t dst, const void* src) {
    asm volatile("cp.async.cg.shared.global [%0], [%1], 16;"
                 :: "r"(dst), "l"(src) : "memory");
}
__device__ __forceinline__ void cp_commit() {
    asm volatile("cp.async.commit_group;" ::: "memory");
}
__device__ __forceinline__ void cp_wait1() {
    asm volatile("cp.async.wait_group 1;" ::: "memory");
}
__device__ __forceinline__ void cp_wait0() {
    asm volatile("cp.async.wait_group 0;" ::: "memory");
}
__device__ __forceinline__ void barg(int id) {   // per-group barrier, 128 thr
    asm volatile("bar.sync %0, 128;" :: "r"(id) : "memory");
}
__device__ __forceinline__ void barall() {       // full CTA
    asm volatile("bar.sync 0, 512;" ::: "memory");
}
__device__ __forceinline__ void ldsm4(uint32_t* r, uint32_t addr) {
    asm volatile("ldmatrix.sync.aligned.m8n8.x4.shared.b16 {%0,%1,%2,%3}, [%4];"
                 : "=r"(r[0]), "=r"(r[1]), "=r"(r[2]), "=r"(r[3]) : "r"(addr));
}
__device__ __forceinline__ void mma_fp16(float* c, const uint32_t* a, const uint32_t* b) {
    asm volatile(
        "mma.sync.aligned.m16n8k16.row.col.f32.f16.f16.f32 "
        "{%0,%1,%2,%3}, {%4,%5,%6,%7}, {%8,%9}, {%0,%1,%2,%3};"
        : "+f"(c[0]), "+f"(c[1]), "+f"(c[2]), "+f"(c[3])
        : "r"(a[0]), "r"(a[1]), "r"(a[2]), "r"(a[3]), "r"(b[0]), "r"(b[1]));
}

// ---------------------------------------------------------------------------
// Prep kernels
// ---------------------------------------------------------------------------
__global__ void k_convert_w(const float* __restrict__ W) {
    int i = blockIdx.x * blockDim.x + threadIdx.x;
    if (i < HH * HH) {
        float w = W[i];
        __half hi = __float2half_rn(w);
        g_whi[i] = hi;
        g_wlo[i] = __float2half_rn(w - __half2float(hi));
    }
}
__global__ void k_init_h() {
    int i = blockIdx.x * blockDim.x + threadIdx.x;
    if (i < BB * HH) g_h[0][i] = __float2half_rn(0.0f);
}

// ---------------------------------------------------------------------------
// One RNN step: D = h @ (Whi + Wlo)^T  (fp16 W-split 2-term on HMMA)
// BK=64, 8 k-iters, swizzled 128B rows. Accumulation order == R13/R14.
// ---------------------------------------------------------------------------
__global__ __launch_bounds__(NTH, 1)
void rnn_step_hmma(const __half* __restrict__ h_in,
                   const float* __restrict__ x,
                   const float* __restrict__ U,
                   const float* __restrict__ bh,
                   __half* __restrict__ h_out,
                   float* __restrict__ fout,
                   int t, int is_last) {
    extern __shared__ __align__(128) char smem[];
    const uint32_t sbase = smem_u32(smem);

    const int tid  = threadIdx.x;
    const int wid  = tid >> 5;
    const int lane = tid & 31;
    const int grp  = tid >> 7;           // 0..3
    const int gwid = wid & 3;
    const int gtid = tid & 127;
    const int n0 = blockIdx.x * BN;
    const int m0 = blockIdx.y * BM;

    const int wm = gwid & 1;
    const int wn = gwid >> 1;
    const int qid = lane >> 2;
    const int rid = lane & 3;

    // ---- R15: per-group phase stagger (timing only, no arithmetic change) ----
    if (grp != 0) {
        const long long skew = (long long)grp * SKEW_CYC;
        const long long t0 = clock64();
        while (clock64() - t0 < skew) { }
    }

    const uint32_t gbase = sbase + (uint32_t)grp * GPIPE;
    const int kbase = grp * KSPLIT;

    // ---- cp.async mapping: 4 chunks/thread/buffer (64 rows x 8 chunks) ----
    int srcoff[4];       // element offset into global row-major tile
    uint32_t dstoff[4];  // byte offset into swizzled smem buffer
    #pragma unroll
    for (int i = 0; i < 4; i++) {
        const int q = gtid + i * 128;
        const int row = q >> 3;
        const int c = q & 7;
        srcoff[i] = row * HH + c * 8;
        dstoff[i] = (uint32_t)(row * ROWB + ((c ^ (row & 7)) << 4));
    }

    const __half* gsrc[3];
    gsrc[0] = h_in  + (size_t)m0 * HH + kbase;
    gsrc[1] = g_whi + (size_t)n0 * HH + kbase;
    gsrc[2] = g_wlo + (size_t)n0 * HH + kbase;

    // ---- ldmatrix lane addressing ----
    const int a_row = (lane & 7) + 8 * ((lane >> 3) & 1);
    const int a_c   = lane >> 4;               // chunk sub-index (0..1)
    const int b_row = ((lane >> 4) << 3) + (lane & 7);
    const int b_c   = (lane >> 3) & 1;

    const int arow0 = wm * 32 + a_row;
    const int brow0 = wn * 32 + b_row;

    float acc[2][4][4];                        // [mt][n8 tile][elem]
    #pragma unroll
    for (int i = 0; i < 2; i++)
        #pragma unroll
        for (int j = 0; j < 4; j++)
            #pragma unroll
            for (int e = 0; e < 4; e++) acc[i][j][e] = 0.0f;

    // ---- prologue: stage 0 ----
    #pragma unroll
    for (int bf = 0; bf < 3; bf++) {
        const uint32_t db = gbase + (uint32_t)(bf * BUFB);
        #pragma unroll
        for (int i = 0; i < 4; i++)
            cp16(db + dstoff[i], gsrc[bf] + srcoff[i]);
    }
    cp_commit();

    const int mybar = grp + 1;                 // named barriers 1..4

    for (int kt = 0; kt < NKT; kt++) {
        const int cur = kt & 1;
        if (kt + 1 < NKT) {
            const uint32_t so = (uint32_t)((kt + 1) & 1) * GSTAGE;
            const int kk = (kt + 1) * BK;
            #pragma unroll
            for (int bf = 0; bf < 3; bf++) {
                const uint32_t db = gbase + so + (uint32_t)(bf * BUFB);
                #pragma unroll
                for (int i = 0; i < 4; i++)
                    cp16(db + dstoff[i], gsrc[bf] + kk + srcoff[i]);
            }
            cp_commit();
            cp_wait1();
        } else {
            cp_wait0();
        }
        barg(mybar);

        const uint32_t sb = gbase + (uint32_t)cur * GSTAGE;
        #pragma unroll
        for (int kh = 0; kh < BK / 16; kh++) {
            uint32_t afr[2][4];
            #pragma unroll
            for (int mt = 0; mt < 2; mt++) {
                const int ar = arow0 + mt * 16;
                const int ac = (kh * 2 + a_c) ^ (ar & 7);
                ldsm4(afr[mt], sb + (0 * BUFB) + (uint32_t)(ar * ROWB + (ac << 4)));
            }
            uint32_t bhi[8], blo[8];
            {
                const int br0 = brow0, br1 = brow0 + 16;
                const int bc0 = (kh * 2 + b_c) ^ (br0 & 7);
                const int bc1 = (kh * 2 + b_c) ^ (br1 & 7);
                ldsm4(bhi,     sb + (1 * BUFB) + (uint32_t)(br0 * ROWB + (bc0 << 4)));
                ldsm4(bhi + 4, sb + (1 * BUFB) + (uint32_t)(br1 * ROWB + (bc1 << 4)));
                ldsm4(blo,     sb + (2 * BUFB) + (uint32_t)(br0 * ROWB + (bc0 << 4)));
                ldsm4(blo + 4, sb + (2 * BUFB) + (uint32_t)(br1 * ROWB + (bc1 << 4)));
            }
            #pragma unroll
            for (int mt = 0; mt < 2; mt++)
                #pragma unroll
                for (int nt = 0; nt < 4; nt++) {
                    mma_fp16(acc[mt][nt], afr[mt], bhi + 2 * nt);
                    mma_fp16(acc[mt][nt], afr[mt], blo + 2 * nt);
                }
        }
        barg(mybar);
    }

    // ---- publish acc into own (now dead) pipeline region ----
    {
        float2* exg = (float2*)(smem + grp * GPIPE);
        #pragma unroll
        for (int mt = 0; mt < 2; mt++)
            #pragma unroll
            for (int nt = 0; nt < 4; nt++) {
                const int p = (mt * 4 + nt) * 2;
                exg[p * 128 + gtid]       = make_float2(acc[mt][nt][0], acc[mt][nt][1]);
                exg[(p + 1) * 128 + gtid] = make_float2(acc[mt][nt][2], acc[mt][nt][3]);
            }
    }
    barall();

    // ---- distributed combine + epilogue: each thread 4 pairs (8 outputs) ----
    {
        const int myMt   = grp >> 1;
        const int ntBase = (grp & 1) * 2;
        const int row0 = m0 + wm * 32 + myMt * 16 + qid;
        const float x0 = x[(size_t)row0 * TT + t];
        const float x1 = x[(size_t)(row0 + 8) * TT + t];

        #pragma unroll
        for (int p = 0; p < 4; p++) {
            const int pglob = grp * 4 + p;
            const int nt = ntBase + (p >> 1);
            const int eh = p & 1;
            const int j  = n0 + wn * 32 + nt * 8 + rid * 2;
            const int row = row0 + eh * 8;
            const float xb = eh ? x1 : x0;

            float sx = 0.0f, sy = 0.0f;
            #pragma unroll
            for (int g = 0; g < 4; g++) {
                float2 v = ((float2*)(smem + g * GPIPE))[pglob * 128 + gtid];
                sx += v.x; sy += v.y;
            }
            const float v0 = tanhf(sx + xb * U[j]     + bh[j]);
            const float v1 = tanhf(sy + xb * U[j + 1] + bh[j + 1]);

            __half hh0 = __float2half_rn(v0);
            __half hh1 = __float2half_rn(v1);
            unsigned short s0 = *(unsigned short*)&hh0;
            unsigned short s1 = *(unsigned short*)&hh1;
            *(uint32_t*)(h_out + (size_t)row * HH + j) = (uint32_t)s0 | ((uint32_t)s1 << 16);
            if (is_last) {
                fout[(size_t)row * HH + j]     = v0;
                fout[(size_t)row * HH + j + 1] = v1;
            }
        }
    }
}

// ---------------------------------------------------------------------------
// Head: out[b,c] = sum_k h[b,k]*V[c,k] + bp[c]
// One block per batch row, one warp per class; shfl reduction.
// ---------------------------------------------------------------------------
__global__ __launch_bounds__(320)
void rnn_head_kernel(const float* __restrict__ h,
                     const float* __restrict__ V,
                     const float* __restrict__ bp,
                     float* __restrict__ out) {
    const int b = blockIdx.x;
    const int c = threadIdx.x >> 5;      // 0..9
    const int lane = threadIdx.x & 31;

    const float* hrow = h + (size_t)b * HH;
    const float* vrow = V + (size_t)c * HH;

    float s = 0.0f;
    #pragma unroll 16
    for (int k = lane; k < HH; k += 32)
        s = fmaf(hrow[k], vrow[k], s);

    #pragma unroll
    for (int o = 16; o > 0; o >>= 1)
        s += __shfl_down_sync(0xFFFFFFFF, s, o);

    if (lane == 0) out[(size_t)b * CC + c] = s + bp[c];
}

// ---------------------------------------------------------------------------
// Host launch
// ---------------------------------------------------------------------------
extern "C" void kernel_launch(void* const* d_in, const int* in_sizes, int n_in,
                              void* d_out, int out_size) {
    const float* x  = (const float*)d_in[0];   // [B, T]
    const float* U  = (const float*)d_in[1];   // [H, 1]
    const float* W  = (const float*)d_in[2];   // [H, H]
    const float* V  = (const float*)d_in[3];   // [C, H]
    const float* bh = (const float*)d_in[4];   // [H]
    const float* bp = (const float*)d_in[5];   // [C]
    float* out = (float*)d_out;                // [B*H + B*C]

    cudaFuncSetAttribute(rnn_step_hmma,
                         cudaFuncAttributeMaxDynamicSharedMemorySize, SMEM_TOTAL);

    void* p_h;
    cudaGetSymbolAddress(&p_h, g_h);
    __half* hbuf = (__half*)p_h;

    // prep: split W into fp16 hi/lo (exact pair), zero h0
    k_convert_w<<<(HH * HH + 255) / 256, 256>>>(W);
    k_init_h<<<(BB * HH + 255) / 256, 256>>>();

    // 128 sequential steps, ping-pong fp16 hidden state
    dim3 grid(HH / BN, BB / BM);  // (32, 4) = 128 CTAs
    for (int t = 0; t < TT; t++) {
        const int inb  = t & 1;
        const int outb = inb ^ 1;
        rnn_step_hmma<<<grid, NTH, SMEM_TOTAL>>>(
            hbuf + (size_t)inb * BB * HH,
            x, U, bh,
            hbuf + (size_t)outb * BB * HH,
            out, t, (t == TT - 1) ? 1 : 0);
    }

    // head on fp32 h_last (written into d_out by last step)
    rnn_head_kernel<<<BB, 320>>>(out, V, bp, out + (size_t)BB * HH);
}